// round 3
// baseline (speedup 1.0000x reference)
#include <cuda_runtime.h>
#include <math.h>
#include <stdint.h>

#define NN   50000
#define EE   800000
#define FIN  64
#define HID  128
#define HEADS 4
#define HOUT 512           // HEADS*HID
#define NLR  1024          // packed xl|xr row width
#define LAYERS 3
#define NEG_SLOPE 0.2f
#define NBCAP 256

// ---------------- scratch (static device globals; no allocations) ----------------
__device__ float g_hA[(size_t)NN * HID];
__device__ float g_hB[(size_t)NN * HID];
__device__ float g_xlr[(size_t)NN * NLR];           // per-node [xl(512) | xr(512)]
__device__ float g_WB[(size_t)LAYERS * HID * NLR];  // packed [Wl | Wr] per layer
__device__ float g_bB[(size_t)LAYERS * NLR];
__device__ int   g_deg[NN];
__device__ int   g_offs[NN + 1];
__device__ int   g_cursor[NN];
__device__ int   g_csr[EE];

// ---------------- weight packing ----------------
__global__ void k_pack(const float* __restrict__ Wl, const float* __restrict__ Wr,
                       const float* __restrict__ bl, const float* __restrict__ br,
                       float* __restrict__ WB, float* __restrict__ bB) {
    int i = blockIdx.x * blockDim.x + threadIdx.x;
    if (i < LAYERS * HID * NLR) {
        int l = i / (HID * NLR);
        int rem = i % (HID * NLR);
        int k = rem / NLR;
        int n = rem % NLR;
        WB[i] = (n < HOUT) ? Wl[((size_t)l * HID + k) * HOUT + n]
                           : Wr[((size_t)l * HID + k) * HOUT + (n - HOUT)];
    }
    if (i < LAYERS * NLR) {
        int l = i / NLR, n = i % NLR;
        bB[i] = (n < HOUT) ? bl[l * HOUT + n] : br[l * HOUT + n - HOUT];
    }
}

// ---------------- CSR build ----------------
__global__ void k_zero_int(int* p, int n) {
    int i = blockIdx.x * blockDim.x + threadIdx.x;
    if (i < n) p[i] = 0;
}

__global__ void k_count_deg(const int* __restrict__ dst, int* __restrict__ deg, int e) {
    int i = blockIdx.x * blockDim.x + threadIdx.x;
    if (i < e) atomicAdd(&deg[dst[i]], 1);
}

__global__ void k_scan_excl(const int* __restrict__ deg, int* __restrict__ offs, int n) {
    __shared__ int sm[1024];
    __shared__ int carry;
    int tid = threadIdx.x;
    if (tid == 0) carry = 0;
    __syncthreads();
    for (int base = 0; base < n; base += 1024) {
        int v = (base + tid < n) ? deg[base + tid] : 0;
        sm[tid] = v;
        __syncthreads();
        for (int d = 1; d < 1024; d <<= 1) {
            int t = (tid >= d) ? sm[tid - d] : 0;
            __syncthreads();
            sm[tid] += t;
            __syncthreads();
        }
        int incl = sm[tid];
        if (base + tid < n) offs[base + tid] = carry + incl - v;
        int total = sm[1023];
        __syncthreads();
        if (tid == 0) carry += total;
        __syncthreads();
    }
    if (tid == 0) offs[n] = carry;
}

__global__ void k_copy_int(const int* __restrict__ a, int* __restrict__ b, int n) {
    int i = blockIdx.x * blockDim.x + threadIdx.x;
    if (i < n) b[i] = a[i];
}

__global__ void k_fill_csr(const int* __restrict__ src, const int* __restrict__ dst,
                           int* __restrict__ cursor, int* __restrict__ csr, int e) {
    int i = blockIdx.x * blockDim.x + threadIdx.x;
    if (i < e) {
        int p = atomicAdd(&cursor[dst[i]], 1);
        csr[p] = src[i];
    }
}

// ---------------- tf32 tensor-core GEMM, 2-stage double buffered ----------------
__device__ __forceinline__ uint32_t f2tf(float f) {
    uint32_t u;
    asm("cvt.rna.tf32.f32 %0, %1;" : "=r"(u) : "f"(f));
    return u;
}

__device__ __forceinline__ void mma_tf32(float* d, const uint32_t* a, const uint32_t* b) {
    asm volatile(
        "mma.sync.aligned.m16n8k8.row.col.f32.tf32.tf32.f32 "
        "{%0,%1,%2,%3}, {%4,%5,%6,%7}, {%8,%9}, {%0,%1,%2,%3};"
        : "+f"(d[0]), "+f"(d[1]), "+f"(d[2]), "+f"(d[3])
        : "r"(a[0]), "r"(a[1]), "r"(a[2]), "r"(a[3]), "r"(b[0]), "r"(b[1]));
}

#define GBM 128
#define GBN 64
#define GBK 32
#define ASTRIDE 36
#define BSTRIDE 68
#define A_TILE (GBM * ASTRIDE)   // 4608 words
#define B_TILE (GBK * BSTRIDE)   // 2176 words
#define GEMM_SMEM ((2 * A_TILE + 2 * B_TILE) * 4)   // 54272 B

template <int KT>
__global__ __launch_bounds__(256) void k_gemm_tf32(
    const float* __restrict__ A, const float* __restrict__ B,
    const float* __restrict__ bias, float* __restrict__ C,
    int M, int N, int relu) {
    extern __shared__ uint32_t smem[];
    uint32_t* Asb[2] = { smem, smem + A_TILE };
    uint32_t* Bsb[2] = { smem + 2 * A_TILE, smem + 2 * A_TILE + B_TILE };
    constexpr int NK = KT / GBK;

    int tid = threadIdx.x;
    int wid = tid >> 5, lane = tid & 31;
    int group = lane >> 2, lig = lane & 3;
    int wm = (wid & 3) * 32;
    int wn = (wid >> 2) * 32;
    int bm = blockIdx.x * GBM, bn = blockIdx.y * GBN;

    // per-thread staging coordinates
    const int a_r = tid >> 3, a_c = (tid & 7) * 4;      // + i*32 rows
    const int b_r = tid >> 4, b_c = (tid & 15) * 4;     // + i*16 rows

    float4 a_reg[4], b_reg[2];

    auto loadG = [&](int kc) {
        #pragma unroll
        for (int i = 0; i < 4; i++) {
            int gr = bm + a_r + i * 32;
            a_reg[i] = (gr < M) ? *(const float4*)(A + (size_t)gr * KT + kc * GBK + a_c)
                                : make_float4(0.f, 0.f, 0.f, 0.f);
        }
        #pragma unroll
        for (int i = 0; i < 2; i++) {
            b_reg[i] = *(const float4*)(B + (size_t)(kc * GBK + b_r + i * 16) * N + bn + b_c);
        }
    };
    auto storeS = [&](int buf) {
        #pragma unroll
        for (int i = 0; i < 4; i++) {
            uint32_t* p = &Asb[buf][(a_r + i * 32) * ASTRIDE + a_c];
            p[0] = f2tf(a_reg[i].x); p[1] = f2tf(a_reg[i].y);
            p[2] = f2tf(a_reg[i].z); p[3] = f2tf(a_reg[i].w);
        }
        #pragma unroll
        for (int i = 0; i < 2; i++) {
            uint32_t* p = &Bsb[buf][(b_r + i * 16) * BSTRIDE + b_c];
            p[0] = f2tf(b_reg[i].x); p[1] = f2tf(b_reg[i].y);
            p[2] = f2tf(b_reg[i].z); p[3] = f2tf(b_reg[i].w);
        }
    };

    float acc[2][4][4];
    #pragma unroll
    for (int i = 0; i < 2; i++)
        #pragma unroll
        for (int j = 0; j < 4; j++)
            #pragma unroll
            for (int k = 0; k < 4; k++) acc[i][j][k] = 0.f;

    loadG(0);
    storeS(0);
    __syncthreads();

    #pragma unroll
    for (int kc = 0; kc < NK; kc++) {
        const int buf = kc & 1;
        if (kc + 1 < NK) loadG(kc + 1);

        const uint32_t* As = Asb[buf];
        const uint32_t* Bs = Bsb[buf];
        #pragma unroll
        for (int k8 = 0; k8 < 4; k8++) {
            uint32_t af[2][4], bf[4][2];
            #pragma unroll
            for (int mt = 0; mt < 2; mt++) {
                int r0 = wm + mt * 16 + group;
                int c0 = k8 * 8 + lig;
                af[mt][0] = As[r0 * ASTRIDE + c0];
                af[mt][1] = As[(r0 + 8) * ASTRIDE + c0];
                af[mt][2] = As[r0 * ASTRIDE + c0 + 4];
                af[mt][3] = As[(r0 + 8) * ASTRIDE + c0 + 4];
            }
            #pragma unroll
            for (int nt = 0; nt < 4; nt++) {
                int c0 = wn + nt * 8 + group;
                int r0 = k8 * 8 + lig;
                bf[nt][0] = Bs[r0 * BSTRIDE + c0];
                bf[nt][1] = Bs[(r0 + 4) * BSTRIDE + c0];
            }
            #pragma unroll
            for (int mt = 0; mt < 2; mt++)
                #pragma unroll
                for (int nt = 0; nt < 4; nt++)
                    mma_tf32(acc[mt][nt], af[mt], bf[nt]);
        }

        if (kc + 1 < NK) storeS((kc + 1) & 1);
        __syncthreads();
    }

    // epilogue: bias + optional relu
    #pragma unroll
    for (int mt = 0; mt < 2; mt++) {
        #pragma unroll
        for (int nt = 0; nt < 4; nt++) {
            int col = bn + wn + nt * 8 + lig * 2;
            float b0 = bias[col], b1 = bias[col + 1];
            int row0 = bm + wm + mt * 16 + group;
            if (row0 < M) {
                float v0 = acc[mt][nt][0] + b0;
                float v1 = acc[mt][nt][1] + b1;
                if (relu) { v0 = fmaxf(v0, 0.f); v1 = fmaxf(v1, 0.f); }
                C[(size_t)row0 * N + col]     = v0;
                C[(size_t)row0 * N + col + 1] = v1;
            }
            int row1 = row0 + 8;
            if (row1 < M) {
                float v2 = acc[mt][nt][2] + b0;
                float v3 = acc[mt][nt][3] + b1;
                if (relu) { v2 = fmaxf(v2, 0.f); v3 = fmaxf(v3, 0.f); }
                C[(size_t)row1 * N + col]     = v2;
                C[(size_t)row1 * N + col + 1] = v3;
            }
        }
    }
}

// ---------------- GATv2 edge kernel: online softmax, smem nbr list, prefetch ----------------
__global__ void k_gat_edge(const float* __restrict__ xlr, const float* __restrict__ att,
                           const float* __restrict__ cbias,
                           const float* __restrict__ hin, float* __restrict__ hout,
                           const int* __restrict__ offs, const int* __restrict__ csr) {
    int node = blockIdx.x;
    int w = threadIdx.x >> 5, lane = threadIdx.x & 31;
    __shared__ float hacc[HEADS][HID];
    __shared__ int nbr[NBCAP];

    int beg = offs[node], end = offs[node + 1];
    int deg = end - beg;

    // stage neighbor indices in smem (coalesced, one shot for deg <= NBCAP)
    for (int i = threadIdx.x; i < deg && i < NBCAP; i += 128) nbr[i] = csr[beg + i];
    __syncthreads();

    const size_t off = (size_t)w * HID + lane * 4;
    const float4 xrv = *(const float4*)(xlr + (size_t)node * NLR + HOUT + off);
    const float4 av  = *(const float4*)(att + w * HID + lane * 4);

    float emax = -1e30f;
    float denom = 0.f;
    float4 acc = make_float4(0.f, 0.f, 0.f, 0.f);

    float4 v = make_float4(0.f, 0.f, 0.f, 0.f);
    if (deg > 0) {
        int s0 = nbr[0];
        v = *(const float4*)(xlr + (size_t)s0 * NLR + off);
    }
    for (int i = 0; i < deg; i++) {
        float4 vn = v;
        if (i + 1 < deg) {
            int sn = (i + 1 < NBCAP) ? nbr[i + 1] : csr[beg + i + 1];
            vn = *(const float4*)(xlr + (size_t)sn * NLR + off);  // prefetch next edge
        }
        float m0 = v.x + xrv.x; m0 = m0 > 0.f ? m0 : NEG_SLOPE * m0;
        float m1 = v.y + xrv.y; m1 = m1 > 0.f ? m1 : NEG_SLOPE * m1;
        float m2 = v.z + xrv.z; m2 = m2 > 0.f ? m2 : NEG_SLOPE * m2;
        float m3 = v.w + xrv.w; m3 = m3 > 0.f ? m3 : NEG_SLOPE * m3;
        float p = av.x * m0 + av.y * m1 + av.z * m2 + av.w * m3;
        #pragma unroll
        for (int o = 16; o; o >>= 1) p += __shfl_xor_sync(0xffffffffu, p, o);
        // p is warp-uniform -> divergence-free rescale
        if (p > emax) {
            float sc = __expf(emax - p);   // first iter: exp(-huge) == 0 wipes state
            denom *= sc;
            acc.x *= sc; acc.y *= sc; acc.z *= sc; acc.w *= sc;
            emax = p;
        }
        float wt = __expf(p - emax);
        denom += wt;
        acc.x += wt * v.x;
        acc.y += wt * v.y;
        acc.z += wt * v.z;
        acc.w += wt * v.w;
        v = vn;
    }
    float inv = denom > 0.f ? 1.f / denom : 0.f;
    hacc[w][lane * 4 + 0] = acc.x * inv;
    hacc[w][lane * 4 + 1] = acc.y * inv;
    hacc[w][lane * 4 + 2] = acc.z * inv;
    hacc[w][lane * 4 + 3] = acc.w * inv;
    __syncthreads();

    int t = threadIdx.x;  // 128 threads == HID
    float sv = (hacc[0][t] + hacc[1][t] + hacc[2][t] + hacc[3][t]) * 0.25f
             + cbias[t] + hin[(size_t)node * HID + t];
    hout[(size_t)node * HID + t] = fmaxf(sv, 0.f);
}

// ---------------- final predictor head ----------------
__global__ void k_pred3(const float* __restrict__ z2, const float* __restrict__ W,
                        const float* __restrict__ b, float* __restrict__ out, int n) {
    int warp = (blockIdx.x * blockDim.x + threadIdx.x) >> 5;
    int lane = threadIdx.x & 31;
    if (warp >= n) return;
    const float* zr = z2 + (size_t)warp * 64;
    float p = zr[lane] * W[lane] + zr[lane + 32] * W[lane + 32];
    #pragma unroll
    for (int o = 16; o; o >>= 1) p += __shfl_xor_sync(0xffffffffu, p, o);
    if (lane == 0) {
        float s = p + b[0];
        s = fminf(fmaxf(s, -15.f), 15.f);
        out[warp] = s;
    }
}

// ---------------- launch ----------------
extern "C" void kernel_launch(void* const* d_in, const int* in_sizes, int n_in,
                              void* d_out, int out_size) {
    const float* x      = (const float*)d_in[0];
    const int*   eidx   = (const int*)d_in[1];
    const float* emb_W  = (const float*)d_in[3];
    const float* emb_b  = (const float*)d_in[4];
    const float* Wl     = (const float*)d_in[5];
    const float* bl     = (const float*)d_in[6];
    const float* Wr     = (const float*)d_in[7];
    const float* br     = (const float*)d_in[8];
    const float* att    = (const float*)d_in[9];
    const float* cbias  = (const float*)d_in[10];
    const float* p1_W   = (const float*)d_in[11];
    const float* p1_b   = (const float*)d_in[12];
    const float* p2_W   = (const float*)d_in[13];
    const float* p2_b   = (const float*)d_in[14];
    const float* p3_W   = (const float*)d_in[15];
    const float* p3_b   = (const float*)d_in[16];
    float* out = (float*)d_out;

    const int* srcp = eidx;
    const int* dstp = eidx + EE;

    float *hA, *hB, *xlr, *WB, *bB;
    int *deg, *offs, *cursor, *csr;
    cudaGetSymbolAddress((void**)&hA, g_hA);
    cudaGetSymbolAddress((void**)&hB, g_hB);
    cudaGetSymbolAddress((void**)&xlr, g_xlr);
    cudaGetSymbolAddress((void**)&WB, g_WB);
    cudaGetSymbolAddress((void**)&bB, g_bB);
    cudaGetSymbolAddress((void**)&deg, g_deg);
    cudaGetSymbolAddress((void**)&offs, g_offs);
    cudaGetSymbolAddress((void**)&cursor, g_cursor);
    cudaGetSymbolAddress((void**)&csr, g_csr);

    cudaFuncSetAttribute(k_gemm_tf32<64>,  cudaFuncAttributeMaxDynamicSharedMemorySize, GEMM_SMEM);
    cudaFuncSetAttribute(k_gemm_tf32<128>, cudaFuncAttributeMaxDynamicSharedMemorySize, GEMM_SMEM);

    // ---- pack weights [Wl|Wr] ----
    k_pack<<<(LAYERS * HID * NLR + 255) / 256, 256>>>(Wl, Wr, bl, br, WB, bB);

    // ---- CSR by dst ----
    k_zero_int<<<(NN + 255) / 256, 256>>>(deg, NN);
    k_count_deg<<<(EE + 255) / 256, 256>>>(dstp, deg, EE);
    k_scan_excl<<<1, 1024>>>(deg, offs, NN);
    k_copy_int<<<(NN + 255) / 256, 256>>>(offs, cursor, NN);
    k_fill_csr<<<(EE + 255) / 256, 256>>>(srcp, dstp, cursor, csr, EE);

    const int MB = (NN + GBM - 1) / GBM;  // 391

    // ---- embedding: h = relu(x @ emb_W + emb_b) ----
    k_gemm_tf32<64><<<dim3(MB, HID / GBN), 256, GEMM_SMEM>>>(x, emb_W, emb_b, hA, NN, HID, 1);

    // ---- 3 GATv2 layers ----
    float* hc = hA;
    float* hn = hB;
    for (int l = 0; l < LAYERS; l++) {
        k_gemm_tf32<128><<<dim3(MB, NLR / GBN), 256, GEMM_SMEM>>>(
            hc, WB + (size_t)l * HID * NLR, bB + (size_t)l * NLR, xlr, NN, NLR, 0);
        k_gat_edge<<<NN, 128>>>(xlr, att + (size_t)l * HEADS * HID, cbias + l * HID,
                                hc, hn, offs, csr);
        float* tmp = hc; hc = hn; hn = tmp;
    }

    // ---- predictor MLP (z1/z2 carved out of xlr scratch) ----
    float* z1 = xlr;
    float* z2 = xlr + (size_t)NN * HID;
    k_gemm_tf32<128><<<dim3(MB, HID / GBN), 256, GEMM_SMEM>>>(hc, p1_W, p1_b, z1, NN, HID, 1);
    k_gemm_tf32<128><<<dim3(MB, 1), 256, GEMM_SMEM>>>(z1, p2_W, p2_b, z2, NN, 64, 1);
    k_pred3<<<(NN * 32 + 255) / 256, 256>>>(z2, p3_W, p3_b, out, NN);
}

// round 4
// speedup vs baseline: 1.0617x; 1.0617x over previous
#include <cuda_runtime.h>
#include <math.h>
#include <stdint.h>

#define NN   50000
#define EE   800000
#define FIN  64
#define HID  128
#define HEADS 4
#define HOUT 512           // HEADS*HID
#define NLR  1024          // packed xl|xr row width
#define LAYERS 3
#define NEG_SLOPE 0.2f
#define SCAN_B 1024
#define NBLK ((NN + SCAN_B - 1) / SCAN_B)   // 49

// ---------------- scratch (static device globals; no allocations) ----------------
__device__ float g_hA[(size_t)NN * HID];
__device__ float g_hB[(size_t)NN * HID];
__device__ float g_xlr[(size_t)NN * NLR];           // per-node [xl(512) | xr(512)]
__device__ float g_WB[(size_t)LAYERS * HID * NLR];  // packed [Wl | Wr] per layer
__device__ float g_bB[(size_t)LAYERS * NLR];
__device__ int   g_deg[NN];
__device__ int   g_offs[NN + 1];
__device__ int   g_cursor[NN];
__device__ int   g_csr[EE];
__device__ int   g_blksum[NBLK];
__device__ int   g_blkoff[NBLK];

// ---------------- weight packing ----------------
__global__ void k_pack(const float* __restrict__ Wl, const float* __restrict__ Wr,
                       const float* __restrict__ bl, const float* __restrict__ br,
                       float* __restrict__ WB, float* __restrict__ bB) {
    int i = blockIdx.x * blockDim.x + threadIdx.x;
    if (i < LAYERS * HID * NLR) {
        int l = i / (HID * NLR);
        int rem = i % (HID * NLR);
        int k = rem / NLR;
        int n = rem % NLR;
        WB[i] = (n < HOUT) ? Wl[((size_t)l * HID + k) * HOUT + n]
                           : Wr[((size_t)l * HID + k) * HOUT + (n - HOUT)];
    }
    if (i < LAYERS * NLR) {
        int l = i / NLR, n = i % NLR;
        bB[i] = (n < HOUT) ? bl[l * HOUT + n] : br[l * HOUT + n - HOUT];
    }
}

// ---------------- CSR build ----------------
__global__ void k_zero_int(int* p, int n) {
    int i = blockIdx.x * blockDim.x + threadIdx.x;
    if (i < n) p[i] = 0;
}

__global__ void k_count_deg(const int* __restrict__ dst, int* __restrict__ deg, int e) {
    int i = blockIdx.x * blockDim.x + threadIdx.x;
    if (i < e) atomicAdd(&deg[dst[i]], 1);
}

// scan stage 1: per-block exclusive scan (warp shuffles), emit block totals
__global__ void k_scan_part(const int* __restrict__ deg, int* __restrict__ offs,
                            int* __restrict__ blksum, int n) {
    __shared__ int wsum[32];
    int gid = blockIdx.x * SCAN_B + threadIdx.x;
    int lane = threadIdx.x & 31, wid = threadIdx.x >> 5;
    int v = (gid < n) ? deg[gid] : 0;
    int s = v;
    #pragma unroll
    for (int o = 1; o < 32; o <<= 1) {
        int t = __shfl_up_sync(0xffffffffu, s, o);
        if (lane >= o) s += t;
    }
    if (lane == 31) wsum[wid] = s;
    __syncthreads();
    if (wid == 0) {
        int ws = wsum[lane];
        #pragma unroll
        for (int o = 1; o < 32; o <<= 1) {
            int t = __shfl_up_sync(0xffffffffu, ws, o);
            if (lane >= o) ws += t;
        }
        wsum[lane] = ws;
    }
    __syncthreads();
    int base = wid ? wsum[wid - 1] : 0;
    int incl = base + s;
    if (gid < n) offs[gid] = incl - v;
    if (threadIdx.x == SCAN_B - 1) blksum[blockIdx.x] = incl;
}

// scan stage 2: scan 49 block totals (single 64-thread block)
__global__ void k_scan_blk(const int* __restrict__ blksum, int* __restrict__ blkoff,
                           int* __restrict__ offs, int nblk, int n) {
    __shared__ int sm[64];
    int t = threadIdx.x;
    int v = (t < nblk) ? blksum[t] : 0;
    sm[t] = v;
    __syncthreads();
    #pragma unroll
    for (int d = 1; d < 64; d <<= 1) {
        int tv = (t >= d) ? sm[t - d] : 0;
        __syncthreads();
        sm[t] += tv;
        __syncthreads();
    }
    if (t < nblk) blkoff[t] = sm[t] - v;
    if (t == 63) offs[n] = sm[63];
}

// scan stage 3: add block offsets; also initialize cursor (replaces k_copy_int)
__global__ void k_scan_add(int* __restrict__ offs, const int* __restrict__ blkoff,
                           int* __restrict__ cursor, int n) {
    int gid = blockIdx.x * SCAN_B + threadIdx.x;
    if (gid < n) {
        int o = offs[gid] + blkoff[blockIdx.x];
        offs[gid] = o;
        cursor[gid] = o;
    }
}

__global__ void k_fill_csr(const int* __restrict__ src, const int* __restrict__ dst,
                           int* __restrict__ cursor, int* __restrict__ csr, int e) {
    int i = blockIdx.x * blockDim.x + threadIdx.x;
    if (i < e) {
        int p = atomicAdd(&cursor[dst[i]], 1);
        csr[p] = src[i];
    }
}

// ---------------- tf32 tensor-core GEMM, 2-stage double buffered ----------------
__device__ __forceinline__ uint32_t f2tf(float f) {
    uint32_t u;
    asm("cvt.rna.tf32.f32 %0, %1;" : "=r"(u) : "f"(f));
    return u;
}

__device__ __forceinline__ void mma_tf32(float* d, const uint32_t* a, const uint32_t* b) {
    asm volatile(
        "mma.sync.aligned.m16n8k8.row.col.f32.tf32.tf32.f32 "
        "{%0,%1,%2,%3}, {%4,%5,%6,%7}, {%8,%9}, {%0,%1,%2,%3};"
        : "+f"(d[0]), "+f"(d[1]), "+f"(d[2]), "+f"(d[3])
        : "r"(a[0]), "r"(a[1]), "r"(a[2]), "r"(a[3]), "r"(b[0]), "r"(b[1]));
}

#define GBM 128
#define GBN 64
#define GBK 32
#define ASTRIDE 36
#define BSTRIDE 68
#define A_TILE (GBM * ASTRIDE)
#define B_TILE (GBK * BSTRIDE)
#define GEMM_SMEM ((2 * A_TILE + 2 * B_TILE) * 4)

template <int KT>
__global__ __launch_bounds__(256) void k_gemm_tf32(
    const float* __restrict__ A, const float* __restrict__ B,
    const float* __restrict__ bias, float* __restrict__ C,
    int M, int N, int relu) {
    extern __shared__ uint32_t smem[];
    uint32_t* Asb[2] = { smem, smem + A_TILE };
    uint32_t* Bsb[2] = { smem + 2 * A_TILE, smem + 2 * A_TILE + B_TILE };
    constexpr int NK = KT / GBK;

    int tid = threadIdx.x;
    int wid = tid >> 5, lane = tid & 31;
    int group = lane >> 2, lig = lane & 3;
    int wm = (wid & 3) * 32;
    int wn = (wid >> 2) * 32;
    int bm = blockIdx.x * GBM, bn = blockIdx.y * GBN;

    const int a_r = tid >> 3, a_c = (tid & 7) * 4;
    const int b_r = tid >> 4, b_c = (tid & 15) * 4;

    float4 a_reg[4], b_reg[2];

    auto loadG = [&](int kc) {
        #pragma unroll
        for (int i = 0; i < 4; i++) {
            int gr = bm + a_r + i * 32;
            a_reg[i] = (gr < M) ? *(const float4*)(A + (size_t)gr * KT + kc * GBK + a_c)
                                : make_float4(0.f, 0.f, 0.f, 0.f);
        }
        #pragma unroll
        for (int i = 0; i < 2; i++) {
            b_reg[i] = *(const float4*)(B + (size_t)(kc * GBK + b_r + i * 16) * N + bn + b_c);
        }
    };
    auto storeS = [&](int buf) {
        #pragma unroll
        for (int i = 0; i < 4; i++) {
            uint32_t* p = &Asb[buf][(a_r + i * 32) * ASTRIDE + a_c];
            p[0] = f2tf(a_reg[i].x); p[1] = f2tf(a_reg[i].y);
            p[2] = f2tf(a_reg[i].z); p[3] = f2tf(a_reg[i].w);
        }
        #pragma unroll
        for (int i = 0; i < 2; i++) {
            uint32_t* p = &Bsb[buf][(b_r + i * 16) * BSTRIDE + b_c];
            p[0] = f2tf(b_reg[i].x); p[1] = f2tf(b_reg[i].y);
            p[2] = f2tf(b_reg[i].z); p[3] = f2tf(b_reg[i].w);
        }
    };

    float acc[2][4][4];
    #pragma unroll
    for (int i = 0; i < 2; i++)
        #pragma unroll
        for (int j = 0; j < 4; j++)
            #pragma unroll
            for (int k = 0; k < 4; k++) acc[i][j][k] = 0.f;

    loadG(0);
    storeS(0);
    __syncthreads();

    #pragma unroll
    for (int kc = 0; kc < NK; kc++) {
        const int buf = kc & 1;
        if (kc + 1 < NK) loadG(kc + 1);

        const uint32_t* As = Asb[buf];
        const uint32_t* Bs = Bsb[buf];
        #pragma unroll
        for (int k8 = 0; k8 < 4; k8++) {
            uint32_t af[2][4], bf[4][2];
            #pragma unroll
            for (int mt = 0; mt < 2; mt++) {
                int r0 = wm + mt * 16 + group;
                int c0 = k8 * 8 + lig;
                af[mt][0] = As[r0 * ASTRIDE + c0];
                af[mt][1] = As[(r0 + 8) * ASTRIDE + c0];
                af[mt][2] = As[r0 * ASTRIDE + c0 + 4];
                af[mt][3] = As[(r0 + 8) * ASTRIDE + c0 + 4];
            }
            #pragma unroll
            for (int nt = 0; nt < 4; nt++) {
                int c0 = wn + nt * 8 + group;
                int r0 = k8 * 8 + lig;
                bf[nt][0] = Bs[r0 * BSTRIDE + c0];
                bf[nt][1] = Bs[(r0 + 4) * BSTRIDE + c0];
            }
            #pragma unroll
            for (int mt = 0; mt < 2; mt++)
                #pragma unroll
                for (int nt = 0; nt < 4; nt++)
                    mma_tf32(acc[mt][nt], af[mt], bf[nt]);
        }

        if (kc + 1 < NK) storeS((kc + 1) & 1);
        __syncthreads();
    }

    #pragma unroll
    for (int mt = 0; mt < 2; mt++) {
        #pragma unroll
        for (int nt = 0; nt < 4; nt++) {
            int col = bn + wn + nt * 8 + lig * 2;
            float b0 = bias[col], b1 = bias[col + 1];
            int row0 = bm + wm + mt * 16 + group;
            if (row0 < M) {
                float v0 = acc[mt][nt][0] + b0;
                float v1 = acc[mt][nt][1] + b1;
                if (relu) { v0 = fmaxf(v0, 0.f); v1 = fmaxf(v1, 0.f); }
                C[(size_t)row0 * N + col]     = v0;
                C[(size_t)row0 * N + col + 1] = v1;
            }
            int row1 = row0 + 8;
            if (row1 < M) {
                float v2 = acc[mt][nt][2] + b0;
                float v3 = acc[mt][nt][3] + b1;
                if (relu) { v2 = fmaxf(v2, 0.f); v3 = fmaxf(v3, 0.f); }
                C[(size_t)row1 * N + col]     = v2;
                C[(size_t)row1 * N + col + 1] = v3;
            }
        }
    }
}

// ---------------- GATv2 edge kernel: pair-unrolled online softmax ----------------
// 256 threads = 2 nodes per block; warp per head within each 128-thread half.
__device__ __forceinline__ float leaky_dot(const float4 av, const float4 v, const float4 xrv) {
    float m0 = v.x + xrv.x; m0 = m0 > 0.f ? m0 : NEG_SLOPE * m0;
    float m1 = v.y + xrv.y; m1 = m1 > 0.f ? m1 : NEG_SLOPE * m1;
    float m2 = v.z + xrv.z; m2 = m2 > 0.f ? m2 : NEG_SLOPE * m2;
    float m3 = v.w + xrv.w; m3 = m3 > 0.f ? m3 : NEG_SLOPE * m3;
    return av.x * m0 + av.y * m1 + av.z * m2 + av.w * m3;
}

__global__ __launch_bounds__(256) void k_gat_edge(
    const float* __restrict__ xlr, const float* __restrict__ att,
    const float* __restrict__ cbias,
    const float* __restrict__ hin, float* __restrict__ hout,
    const int* __restrict__ offs, const int* __restrict__ csr) {
    int half = threadIdx.x >> 7;           // 0 or 1
    int node = blockIdx.x * 2 + half;
    int t128 = threadIdx.x & 127;
    int w = t128 >> 5, lane = threadIdx.x & 31;
    __shared__ float hacc[2][HEADS][HID];

    float emax = -1e30f, denom = 0.f;
    float4 acc = make_float4(0.f, 0.f, 0.f, 0.f);
    size_t nodebase = 0;

    if (node < NN) {
        int beg = offs[node], end = offs[node + 1];
        nodebase = (size_t)node * NLR;
        const size_t off = (size_t)w * HID + lane * 4;
        const float4 xrv = *(const float4*)(xlr + nodebase + HOUT + off);
        const float4 av  = *(const float4*)(att + w * HID + lane * 4);

        int i = beg;
        for (; i + 1 < end; i += 2) {
            int s0 = __ldg(csr + i), s1 = __ldg(csr + i + 1);
            float4 v0 = *(const float4*)(xlr + (size_t)s0 * NLR + off);
            float4 v1 = *(const float4*)(xlr + (size_t)s1 * NLR + off);
            float p0 = leaky_dot(av, v0, xrv);
            float p1 = leaky_dot(av, v1, xrv);
            #pragma unroll
            for (int o = 16; o; o >>= 1) {
                p0 += __shfl_xor_sync(0xffffffffu, p0, o);
                p1 += __shfl_xor_sync(0xffffffffu, p1, o);
            }
            float nm = fmaxf(emax, fmaxf(p0, p1));
            float sc = __expf(emax - nm);     // ==1 when no new max; exp(-huge)=0 on first
            denom *= sc;
            acc.x *= sc; acc.y *= sc; acc.z *= sc; acc.w *= sc;
            emax = nm;
            float w0 = __expf(p0 - nm), w1 = __expf(p1 - nm);
            denom += w0 + w1;
            acc.x += w0 * v0.x + w1 * v1.x;
            acc.y += w0 * v0.y + w1 * v1.y;
            acc.z += w0 * v0.z + w1 * v1.z;
            acc.w += w0 * v0.w + w1 * v1.w;
        }
        if (i < end) {
            int s0 = __ldg(csr + i);
            float4 v0 = *(const float4*)(xlr + (size_t)s0 * NLR + off);
            float p0 = leaky_dot(av, v0, xrv);
            #pragma unroll
            for (int o = 16; o; o >>= 1) p0 += __shfl_xor_sync(0xffffffffu, p0, o);
            float nm = fmaxf(emax, p0);
            float sc = __expf(emax - nm);
            denom *= sc;
            acc.x *= sc; acc.y *= sc; acc.z *= sc; acc.w *= sc;
            emax = nm;
            float w0 = __expf(p0 - nm);
            denom += w0;
            acc.x += w0 * v0.x; acc.y += w0 * v0.y;
            acc.z += w0 * v0.z; acc.w += w0 * v0.w;
        }
        float inv = denom > 0.f ? 1.f / denom : 0.f;
        hacc[half][w][lane * 4 + 0] = acc.x * inv;
        hacc[half][w][lane * 4 + 1] = acc.y * inv;
        hacc[half][w][lane * 4 + 2] = acc.z * inv;
        hacc[half][w][lane * 4 + 3] = acc.w * inv;
    }
    __syncthreads();
    if (node < NN) {
        float sv = (hacc[half][0][t128] + hacc[half][1][t128] +
                    hacc[half][2][t128] + hacc[half][3][t128]) * 0.25f
                 + cbias[t128] + hin[(size_t)node * HID + t128];
        hout[(size_t)node * HID + t128] = fmaxf(sv, 0.f);
    }
}

// ---------------- final predictor head ----------------
__global__ void k_pred3(const float* __restrict__ z2, const float* __restrict__ W,
                        const float* __restrict__ b, float* __restrict__ out, int n) {
    int warp = (blockIdx.x * blockDim.x + threadIdx.x) >> 5;
    int lane = threadIdx.x & 31;
    if (warp >= n) return;
    const float* zr = z2 + (size_t)warp * 64;
    float p = zr[lane] * W[lane] + zr[lane + 32] * W[lane + 32];
    #pragma unroll
    for (int o = 16; o; o >>= 1) p += __shfl_xor_sync(0xffffffffu, p, o);
    if (lane == 0) {
        float s = p + b[0];
        s = fminf(fmaxf(s, -15.f), 15.f);
        out[warp] = s;
    }
}

// ---------------- launch ----------------
extern "C" void kernel_launch(void* const* d_in, const int* in_sizes, int n_in,
                              void* d_out, int out_size) {
    const float* x      = (const float*)d_in[0];
    const int*   eidx   = (const int*)d_in[1];
    const float* emb_W  = (const float*)d_in[3];
    const float* emb_b  = (const float*)d_in[4];
    const float* Wl     = (const float*)d_in[5];
    const float* bl     = (const float*)d_in[6];
    const float* Wr     = (const float*)d_in[7];
    const float* br     = (const float*)d_in[8];
    const float* att    = (const float*)d_in[9];
    const float* cbias  = (const float*)d_in[10];
    const float* p1_W   = (const float*)d_in[11];
    const float* p1_b   = (const float*)d_in[12];
    const float* p2_W   = (const float*)d_in[13];
    const float* p2_b   = (const float*)d_in[14];
    const float* p3_W   = (const float*)d_in[15];
    const float* p3_b   = (const float*)d_in[16];
    float* out = (float*)d_out;

    const int* srcp = eidx;
    const int* dstp = eidx + EE;

    float *hA, *hB, *xlr, *WB, *bB;
    int *deg, *offs, *cursor, *csr, *blksum, *blkoff;
    cudaGetSymbolAddress((void**)&hA, g_hA);
    cudaGetSymbolAddress((void**)&hB, g_hB);
    cudaGetSymbolAddress((void**)&xlr, g_xlr);
    cudaGetSymbolAddress((void**)&WB, g_WB);
    cudaGetSymbolAddress((void**)&bB, g_bB);
    cudaGetSymbolAddress((void**)&deg, g_deg);
    cudaGetSymbolAddress((void**)&offs, g_offs);
    cudaGetSymbolAddress((void**)&cursor, g_cursor);
    cudaGetSymbolAddress((void**)&csr, g_csr);
    cudaGetSymbolAddress((void**)&blksum, g_blksum);
    cudaGetSymbolAddress((void**)&blkoff, g_blkoff);

    cudaFuncSetAttribute(k_gemm_tf32<64>,  cudaFuncAttributeMaxDynamicSharedMemorySize, GEMM_SMEM);
    cudaFuncSetAttribute(k_gemm_tf32<128>, cudaFuncAttributeMaxDynamicSharedMemorySize, GEMM_SMEM);

    const int MB = (NN + GBM - 1) / GBM;  // 391

    // Order chosen so the big layer-1 GEMM is the 4th launch (ncu capture slot).
    // (1) embedding
    k_gemm_tf32<64><<<dim3(MB, HID / GBN), 256, GEMM_SMEM>>>(x, emb_W, emb_b, hA, NN, HID, 1);
    // (2) pack weights
    k_pack<<<(LAYERS * HID * NLR + 255) / 256, 256>>>(Wl, Wr, bl, br, WB, bB);
    // (3) zero degrees
    k_zero_int<<<(NN + 255) / 256, 256>>>(deg, NN);
    // (4) layer-1 xlr GEMM  <-- profiled
    k_gemm_tf32<128><<<dim3(MB, NLR / GBN), 256, GEMM_SMEM>>>(hA, WB, bB, xlr, NN, NLR, 0);
    // CSR build
    k_count_deg<<<(EE + 255) / 256, 256>>>(dstp, deg, EE);
    k_scan_part<<<NBLK, SCAN_B>>>(deg, offs, blksum, NN);
    k_scan_blk<<<1, 64>>>(blksum, blkoff, offs, NBLK, NN);
    k_scan_add<<<NBLK, SCAN_B>>>(offs, blkoff, cursor, NN);
    k_fill_csr<<<(EE + 255) / 256, 256>>>(srcp, dstp, cursor, csr, EE);

    // layer 1 edge
    float* hc = hA;
    float* hn = hB;
    k_gat_edge<<<(NN + 1) / 2, 256>>>(xlr, att, cbias, hc, hn, offs, csr);
    { float* t = hc; hc = hn; hn = t; }

    // layers 2..3
    for (int l = 1; l < LAYERS; l++) {
        k_gemm_tf32<128><<<dim3(MB, NLR / GBN), 256, GEMM_SMEM>>>(
            hc, WB + (size_t)l * HID * NLR, bB + (size_t)l * NLR, xlr, NN, NLR, 0);
        k_gat_edge<<<(NN + 1) / 2, 256>>>(xlr, att + (size_t)l * HEADS * HID,
                                          cbias + l * HID, hc, hn, offs, csr);
        float* t = hc; hc = hn; hn = t;
    }

    // predictor MLP (z1/z2 carved out of xlr scratch)
    float* z1 = xlr;
    float* z2 = xlr + (size_t)NN * HID;
    k_gemm_tf32<128><<<dim3(MB, HID / GBN), 256, GEMM_SMEM>>>(hc, p1_W, p1_b, z1, NN, HID, 1);
    k_gemm_tf32<128><<<dim3(MB, 1), 256, GEMM_SMEM>>>(z1, p2_W, p2_b, z2, NN, 64, 1);
    k_pred3<<<(NN * 32 + 255) / 256, 256>>>(z2, p3_W, p3_b, out, NN);
}

// round 6
// speedup vs baseline: 1.1778x; 1.1093x over previous
#include <cuda_runtime.h>
#include <math.h>
#include <stdint.h>

#define NN   50000
#define EE   800000
#define FIN  64
#define HID  128
#define HEADS 4
#define HOUT 512           // HEADS*HID
#define NLR  1024          // packed xl|xr row width
#define LAYERS 3
#define NEG_SLOPE 0.2f
#define SCAN_B 1024
#define NBLK ((NN + SCAN_B - 1) / SCAN_B)   // 49

// ---------------- scratch (static device globals; no allocations) ----------------
__device__ float g_hA[(size_t)NN * HID];
__device__ float g_hB[(size_t)NN * HID];
__device__ float g_xlr[(size_t)NN * NLR];           // per-node [xl(512) | xr(512)]
__device__ float g_WB[(size_t)LAYERS * HID * NLR];  // packed [Wl | Wr] per layer, [k][n]
__device__ float g_bB[(size_t)LAYERS * NLR];
__device__ float g_p2p[128 * 128];                  // p2 weights zero-padded to [128][128]
__device__ float g_p2b[128];
__device__ int   g_deg[NN];
__device__ int   g_offs[NN + 1];
__device__ int   g_cursor[NN];
__device__ int   g_csr[EE];
__device__ int   g_blksum[NBLK];
__device__ int   g_blkoff[NBLK];

// ---------------- prep: pack [Wl|Wr] (K-major) + pad p2 ----------------
__global__ void k_prep(const float* __restrict__ Wl, const float* __restrict__ Wr,
                       const float* __restrict__ bl, const float* __restrict__ br,
                       const float* __restrict__ p2_W, const float* __restrict__ p2_b,
                       float* __restrict__ WB, float* __restrict__ bB,
                       float* __restrict__ p2p, float* __restrict__ p2bp) {
    int i = blockIdx.x * blockDim.x + threadIdx.x;
    if (i < LAYERS * HID * NLR) {       // WB[l][k][n]
        int l = i / (HID * NLR);
        int rem = i % (HID * NLR);
        int k = rem / NLR, n = rem % NLR;
        WB[i] = (n < HOUT) ? Wl[((size_t)l * HID + k) * HOUT + n]
                           : Wr[((size_t)l * HID + k) * HOUT + (n - HOUT)];
    }
    if (i < LAYERS * NLR) {
        int l = i / NLR, n = i % NLR;
        bB[i] = (n < HOUT) ? bl[l * HOUT + n] : br[l * HOUT + n - HOUT];
    }
    if (i < 128 * 128) {
        int k = i >> 7, n = i & 127;
        p2p[i] = (n < 64) ? p2_W[k * 64 + n] : 0.f;
    }
    if (i < 128) p2bp[i] = (i < 64) ? p2_b[i] : 0.f;
}

// ---------------- CSR build ----------------
__global__ void k_zero_int(int* p, int n) {
    int i = blockIdx.x * blockDim.x + threadIdx.x;
    if (i < n) p[i] = 0;
}
__global__ void k_count_deg(const int* __restrict__ dst, int* __restrict__ deg, int e) {
    int i = blockIdx.x * blockDim.x + threadIdx.x;
    if (i < e) atomicAdd(&deg[dst[i]], 1);
}
__global__ void k_scan_part(const int* __restrict__ deg, int* __restrict__ offs,
                            int* __restrict__ blksum, int n) {
    __shared__ int wsum[32];
    int gid = blockIdx.x * SCAN_B + threadIdx.x;
    int lane = threadIdx.x & 31, wid = threadIdx.x >> 5;
    int v = (gid < n) ? deg[gid] : 0;
    int s = v;
    #pragma unroll
    for (int o = 1; o < 32; o <<= 1) {
        int t = __shfl_up_sync(0xffffffffu, s, o);
        if (lane >= o) s += t;
    }
    if (lane == 31) wsum[wid] = s;
    __syncthreads();
    if (wid == 0) {
        int ws = wsum[lane];
        #pragma unroll
        for (int o = 1; o < 32; o <<= 1) {
            int t = __shfl_up_sync(0xffffffffu, ws, o);
            if (lane >= o) ws += t;
        }
        wsum[lane] = ws;
    }
    __syncthreads();
    int base = wid ? wsum[wid - 1] : 0;
    int incl = base + s;
    if (gid < n) offs[gid] = incl - v;
    if (threadIdx.x == SCAN_B - 1) blksum[blockIdx.x] = incl;
}
__global__ void k_scan_blk(const int* __restrict__ blksum, int* __restrict__ blkoff,
                           int* __restrict__ offs, int nblk, int n) {
    __shared__ int sm[64];
    int t = threadIdx.x;
    int v = (t < nblk) ? blksum[t] : 0;
    sm[t] = v;
    __syncthreads();
    #pragma unroll
    for (int d = 1; d < 64; d <<= 1) {
        int tv = (t >= d) ? sm[t - d] : 0;
        __syncthreads();
        sm[t] += tv;
        __syncthreads();
    }
    if (t < nblk) blkoff[t] = sm[t] - v;
    if (t == 63) offs[n] = sm[63];
}
__global__ void k_scan_add(int* __restrict__ offs, const int* __restrict__ blkoff,
                           int* __restrict__ cursor, int n) {
    int gid = blockIdx.x * SCAN_B + threadIdx.x;
    if (gid < n) {
        int o = offs[gid] + blkoff[blockIdx.x];
        offs[gid] = o;
        cursor[gid] = o;
    }
}
__global__ void k_fill_csr(const int* __restrict__ src, const int* __restrict__ dst,
                           int* __restrict__ cursor, int* __restrict__ csr, int e) {
    int i = blockIdx.x * blockDim.x + threadIdx.x;
    if (i < e) {
        int p = atomicAdd(&cursor[dst[i]], 1);
        csr[p] = src[i];
    }
}

// ---------------- tf32 mma.sync GEMM, fragment-native permuted smem ----------------
// Block 128x128, 8 warps of 64x32 tiles. C = act(A[M,KT] @ B[KT,N] + bias).
// A smem: per chunk [wmB(2)][mt(4)][k8(4)] x 32 lanes x 4 frags, lane-XOR k8 (LDS.128).
// B smem: per chunk [wnB(4)][nt(4)][k8(4)] x 32 lanes x 2 slots, lane-XOR (nt<<2)^wnB (LDS.64).

__device__ __forceinline__ uint32_t f2tf(float f) {
    uint32_t u;
    asm("cvt.rna.tf32.f32 %0, %1;" : "=r"(u) : "f"(f));
    return u;
}
__device__ __forceinline__ void mma_tf32(float* d, const uint32_t* a, const uint32_t* b) {
    asm volatile(
        "mma.sync.aligned.m16n8k8.row.col.f32.tf32.tf32.f32 "
        "{%0,%1,%2,%3}, {%4,%5,%6,%7}, {%8,%9}, {%0,%1,%2,%3};"
        : "+f"(d[0]), "+f"(d[1]), "+f"(d[2]), "+f"(d[3])
        : "r"(a[0]), "r"(a[1]), "r"(a[2]), "r"(a[3]), "r"(b[0]), "r"(b[1]));
}

#define G2_SMEM 65536   // 2 bufs x (A 4096 + B 4096) words

template <int KT>
__global__ __launch_bounds__(256, 2) void k_gemm2(
    const float* __restrict__ A, const float* __restrict__ B,
    const float* __restrict__ bias, float* __restrict__ C,
    int M, int Ns, int relu) {
    extern __shared__ uint32_t sm[];
    constexpr int NK = KT / 32;
    int tid = threadIdx.x;
    int wid = tid >> 5, lane = tid & 31;
    int group = lane >> 2, lig = lane & 3;
    const int wm = (wid & 1) * 64;      // warp row offset
    const int wn = (wid >> 1) * 32;     // warp col offset
    const int wmB_w = wid & 1;
    const int wnB_w = wid >> 1;
    const int bm = blockIdx.x * 128, bn = blockIdx.y * 128;

    // staging coords
    const int a_r = tid >> 3;            // +32*i
    const int a_c = (tid & 7) * 4;       // chunk col
    const int b_r = tid >> 5;            // +8*i (k row in chunk)
    const int b_c = (tid & 31) * 4;      // n col in block

    // precomputed A staging constants
    const int a_k8 = a_c >> 3;
    const int a_sc = (a_c >> 2) & 1;
    // precomputed B staging constants
    const int b_wnB = b_c >> 5;
    const int b_cc = b_c & 31;
    const int b_nt = b_cc >> 3;
    const int b_g0 = b_cc & 7;          // 0 or 4

    float acc[4][4][4];
    #pragma unroll
    for (int i = 0; i < 4; i++)
        #pragma unroll
        for (int j = 0; j < 4; j++)
            #pragma unroll
            for (int q = 0; q < 4; q++) acc[i][j][q] = 0.f;

    int buf = 0;
    // stage chunk kc into buffer b
    auto stage = [&](int kc, int bsel) {
        uint32_t* As = sm + bsel * 8192;
        uint32_t* Bs = As + 4096;
        #pragma unroll
        for (int i = 0; i < 4; i++) {
            int r = a_r + 32 * i;
            int gr = bm + r;
            float4 v = (gr < M) ? *(const float4*)(A + (size_t)gr * KT + kc * 32 + a_c)
                                : make_float4(0.f, 0.f, 0.f, 0.f);
            int wmB = r >> 6, mt = (r >> 4) & 3, rsub = r & 15;
            int hi = rsub >> 3, grp = rsub & 7;
            int frag = a_sc * 2 + hi;
            uint32_t base = (uint32_t)(((wmB * 4 + mt) * 4 + a_k8) * 128 + grp * 16 + frag);
            As[base + (((0 ^ a_k8)) << 2)] = f2tf(v.x);
            As[base + (((1 ^ a_k8)) << 2)] = f2tf(v.y);
            As[base + (((2 ^ a_k8)) << 2)] = f2tf(v.z);
            As[base + (((3 ^ a_k8)) << 2)] = f2tf(v.w);
        }
        #pragma unroll
        for (int i = 0; i < 4; i++) {
            int rB = b_r + 8 * i;
            float4 v = *(const float4*)(B + (size_t)(kc * 32 + rB) * Ns + bn + b_c);
            int k8 = rB >> 3, rr = rB & 7;
            int lg = rr & 3, slot = rr >> 2;
            uint32_t base = (uint32_t)(((b_wnB * 4 + b_nt) * 4 + k8) * 64
                                       + (b_g0 * 4 + (lg ^ b_wnB)) * 2 + slot);
            Bs[base + ((0 ^ b_nt) << 3)] = f2tf(v.x);
            Bs[base + ((1 ^ b_nt) << 3)] = f2tf(v.y);
            Bs[base + ((2 ^ b_nt) << 3)] = f2tf(v.z);
            Bs[base + ((3 ^ b_nt) << 3)] = f2tf(v.w);
        }
    };

    stage(0, 0);
    __syncthreads();

    #pragma unroll
    for (int kc = 0; kc < NK; kc++) {
        if (kc + 1 < NK) stage(kc + 1, buf ^ 1);

        const uint32_t* As = sm + buf * 8192;
        const uint32_t* Bs = As + 4096;
        #pragma unroll
        for (int k8 = 0; k8 < 4; k8++) {
            uint4 af[4];
            #pragma unroll
            for (int mt = 0; mt < 4; mt++) {
                uint32_t w = (uint32_t)(((wmB_w * 4 + mt) * 4 + k8) * 128 + ((lane ^ k8) << 2));
                af[mt] = *(const uint4*)(As + w);
            }
            uint2 bf[4];
            #pragma unroll
            for (int nt = 0; nt < 4; nt++) {
                uint32_t w = (uint32_t)(((wnB_w * 4 + nt) * 4 + k8) * 64
                                        + ((lane ^ (nt << 2) ^ wnB_w) << 1));
                bf[nt] = *(const uint2*)(Bs + w);
            }
            #pragma unroll
            for (int mt = 0; mt < 4; mt++)
                #pragma unroll
                for (int nt = 0; nt < 4; nt++)
                    mma_tf32(acc[mt][nt], (const uint32_t*)&af[mt], (const uint32_t*)&bf[nt]);
        }
        __syncthreads();
        buf ^= 1;
    }

    // epilogue
    #pragma unroll
    for (int mt = 0; mt < 4; mt++) {
        #pragma unroll
        for (int nt = 0; nt < 4; nt++) {
            int col = bn + wn + nt * 8 + lig * 2;
            float b0 = __ldg(bias + col), b1 = __ldg(bias + col + 1);
            int row0 = bm + wm + mt * 16 + group;
            if (row0 < M) {
                float v0 = acc[mt][nt][0] + b0;
                float v1 = acc[mt][nt][1] + b1;
                if (relu) { v0 = fmaxf(v0, 0.f); v1 = fmaxf(v1, 0.f); }
                float2 o = make_float2(v0, v1);
                *(float2*)(C + (size_t)row0 * Ns + col) = o;
            }
            int row1 = row0 + 8;
            if (row1 < M) {
                float v2 = acc[mt][nt][2] + b0;
                float v3 = acc[mt][nt][3] + b1;
                if (relu) { v2 = fmaxf(v2, 0.f); v3 = fmaxf(v3, 0.f); }
                float2 o = make_float2(v2, v3);
                *(float2*)(C + (size_t)row1 * Ns + col) = o;
            }
        }
    }
}

// ---------------- GATv2 edge kernel: pair-unrolled online softmax ----------------
__device__ __forceinline__ float leaky_dot(const float4 av, const float4 v, const float4 xrv) {
    float m0 = v.x + xrv.x; m0 = m0 > 0.f ? m0 : NEG_SLOPE * m0;
    float m1 = v.y + xrv.y; m1 = m1 > 0.f ? m1 : NEG_SLOPE * m1;
    float m2 = v.z + xrv.z; m2 = m2 > 0.f ? m2 : NEG_SLOPE * m2;
    float m3 = v.w + xrv.w; m3 = m3 > 0.f ? m3 : NEG_SLOPE * m3;
    return av.x * m0 + av.y * m1 + av.z * m2 + av.w * m3;
}

__global__ __launch_bounds__(256) void k_gat_edge(
    const float* __restrict__ xlr, const float* __restrict__ att,
    const float* __restrict__ cbias,
    const float* __restrict__ hin, float* __restrict__ hout,
    const int* __restrict__ offs, const int* __restrict__ csr) {
    int half = threadIdx.x >> 7;
    int node = blockIdx.x * 2 + half;
    int t128 = threadIdx.x & 127;
    int w = t128 >> 5, lane = threadIdx.x & 31;
    __shared__ float hacc[2][HEADS][HID];

    if (node < NN) {
        int beg = offs[node], end = offs[node + 1];
        const size_t off = (size_t)w * HID + lane * 4;
        const float4 xrv = *(const float4*)(xlr + (size_t)node * NLR + HOUT + off);
        const float4 av  = *(const float4*)(att + w * HID + lane * 4);

        float emax = -1e30f, denom = 0.f;
        float4 acc = make_float4(0.f, 0.f, 0.f, 0.f);
        int i = beg;
        for (; i + 1 < end; i += 2) {
            int s0 = __ldg(csr + i), s1 = __ldg(csr + i + 1);
            float4 v0 = *(const float4*)(xlr + (size_t)s0 * NLR + off);
            float4 v1 = *(const float4*)(xlr + (size_t)s1 * NLR + off);
            float p0 = leaky_dot(av, v0, xrv);
            float p1 = leaky_dot(av, v1, xrv);
            #pragma unroll
            for (int o = 16; o; o >>= 1) {
                p0 += __shfl_xor_sync(0xffffffffu, p0, o);
                p1 += __shfl_xor_sync(0xffffffffu, p1, o);
            }
            float nm = fmaxf(emax, fmaxf(p0, p1));
            float sc = __expf(emax - nm);
            denom *= sc;
            acc.x *= sc; acc.y *= sc; acc.z *= sc; acc.w *= sc;
            emax = nm;
            float w0 = __expf(p0 - nm), w1 = __expf(p1 - nm);
            denom += w0 + w1;
            acc.x += w0 * v0.x + w1 * v1.x;
            acc.y += w0 * v0.y + w1 * v1.y;
            acc.z += w0 * v0.z + w1 * v1.z;
            acc.w += w0 * v0.w + w1 * v1.w;
        }
        if (i < end) {
            int s0 = __ldg(csr + i);
            float4 v0 = *(const float4*)(xlr + (size_t)s0 * NLR + off);
            float p0 = leaky_dot(av, v0, xrv);
            #pragma unroll
            for (int o = 16; o; o >>= 1) p0 += __shfl_xor_sync(0xffffffffu, p0, o);
            float nm = fmaxf(emax, p0);
            float sc = __expf(emax - nm);
            denom *= sc;
            acc.x *= sc; acc.y *= sc; acc.z *= sc; acc.w *= sc;
            emax = nm;
            float w0 = __expf(p0 - nm);
            denom += w0;
            acc.x += w0 * v0.x; acc.y += w0 * v0.y;
            acc.z += w0 * v0.z; acc.w += w0 * v0.w;
        }
        float inv = denom > 0.f ? 1.f / denom : 0.f;
        hacc[half][w][lane * 4 + 0] = acc.x * inv;
        hacc[half][w][lane * 4 + 1] = acc.y * inv;
        hacc[half][w][lane * 4 + 2] = acc.z * inv;
        hacc[half][w][lane * 4 + 3] = acc.w * inv;
    }
    __syncthreads();
    if (node < NN) {
        float sv = (hacc[half][0][t128] + hacc[half][1][t128] +
                    hacc[half][2][t128] + hacc[half][3][t128]) * 0.25f
                 + cbias[t128] + hin[(size_t)node * HID + t128];
        hout[(size_t)node * HID + t128] = fmaxf(sv, 0.f);
    }
}

// ---------------- final predictor head (z2 row stride 128) ----------------
__global__ void k_pred3(const float* __restrict__ z2, const float* __restrict__ W,
                        const float* __restrict__ b, float* __restrict__ out, int n) {
    int warp = (blockIdx.x * blockDim.x + threadIdx.x) >> 5;
    int lane = threadIdx.x & 31;
    if (warp >= n) return;
    const float* zr = z2 + (size_t)warp * 128;
    float p = zr[lane] * W[lane] + zr[lane + 32] * W[lane + 32];
    #pragma unroll
    for (int o = 16; o; o >>= 1) p += __shfl_xor_sync(0xffffffffu, p, o);
    if (lane == 0) {
        float s = p + b[0];
        s = fminf(fmaxf(s, -15.f), 15.f);
        out[warp] = s;
    }
}

// ---------------- launch ----------------
extern "C" void kernel_launch(void* const* d_in, const int* in_sizes, int n_in,
                              void* d_out, int out_size) {
    const float* x      = (const float*)d_in[0];
    const int*   eidx   = (const int*)d_in[1];
    const float* emb_W  = (const float*)d_in[3];
    const float* emb_b  = (const float*)d_in[4];
    const float* Wl     = (const float*)d_in[5];
    const float* bl     = (const float*)d_in[6];
    const float* Wr     = (const float*)d_in[7];
    const float* br     = (const float*)d_in[8];
    const float* att    = (const float*)d_in[9];
    const float* cbias  = (const float*)d_in[10];
    const float* p1_W   = (const float*)d_in[11];
    const float* p1_b   = (const float*)d_in[12];
    const float* p2_W   = (const float*)d_in[13];
    const float* p2_b   = (const float*)d_in[14];
    const float* p3_W   = (const float*)d_in[15];
    const float* p3_b   = (const float*)d_in[16];
    float* out = (float*)d_out;

    const int* srcp = eidx;
    const int* dstp = eidx + EE;

    float *hA, *hB, *xlr, *WB, *bB, *p2p, *p2b;
    int *deg, *offs, *cursor, *csr, *blksum, *blkoff;
    cudaGetSymbolAddress((void**)&hA, g_hA);
    cudaGetSymbolAddress((void**)&hB, g_hB);
    cudaGetSymbolAddress((void**)&xlr, g_xlr);
    cudaGetSymbolAddress((void**)&WB, g_WB);
    cudaGetSymbolAddress((void**)&bB, g_bB);
    cudaGetSymbolAddress((void**)&p2p, g_p2p);
    cudaGetSymbolAddress((void**)&p2b, g_p2b);
    cudaGetSymbolAddress((void**)&deg, g_deg);
    cudaGetSymbolAddress((void**)&offs, g_offs);
    cudaGetSymbolAddress((void**)&cursor, g_cursor);
    cudaGetSymbolAddress((void**)&csr, g_csr);
    cudaGetSymbolAddress((void**)&blksum, g_blksum);
    cudaGetSymbolAddress((void**)&blkoff, g_blkoff);

    cudaFuncSetAttribute(k_gemm2<64>,  cudaFuncAttributeMaxDynamicSharedMemorySize, G2_SMEM);
    cudaFuncSetAttribute(k_gemm2<128>, cudaFuncAttributeMaxDynamicSharedMemorySize, G2_SMEM);

    const int MB = (NN + 127) / 128;  // 391

    // (1) prep: pack [Wl|Wr], pad p2
    k_prep<<<(LAYERS * HID * NLR + 255) / 256, 256>>>(Wl, Wr, bl, br, p2_W, p2_b,
                                                      WB, bB, p2p, p2b);
    // (2) embedding: h = relu(x @ emb_W + emb_b)   (K=64, N=128)
    k_gemm2<64><<<dim3(MB, 1), 256, G2_SMEM>>>(x, emb_W, emb_b, hA, NN, HID, 1);
    // (3) zero degrees
    k_zero_int<<<(NN + 255) / 256, 256>>>(deg, NN);
    // (4) layer-1 xlr GEMM  <-- profiled slot
    k_gemm2<128><<<dim3(MB, NLR / 128), 256, G2_SMEM>>>(hA, WB, bB, xlr, NN, NLR, 0);
    // CSR build
    k_count_deg<<<(EE + 255) / 256, 256>>>(dstp, deg, EE);
    k_scan_part<<<NBLK, SCAN_B>>>(deg, offs, blksum, NN);
    k_scan_blk<<<1, 64>>>(blksum, blkoff, offs, NBLK, NN);
    k_scan_add<<<NBLK, SCAN_B>>>(offs, blkoff, cursor, NN);
    k_fill_csr<<<(EE + 255) / 256, 256>>>(srcp, dstp, cursor, csr, EE);

    // layer 1 edge
    float* hc = hA;
    float* hn = hB;
    k_gat_edge<<<(NN + 1) / 2, 256>>>(xlr, att, cbias, hc, hn, offs, csr);
    { float* t = hc; hc = hn; hn = t; }

    // layers 2..3
    for (int l = 1; l < LAYERS; l++) {
        k_gemm2<128><<<dim3(MB, NLR / 128), 256, G2_SMEM>>>(
            hc, WB + (size_t)l * HID * NLR, bB + (size_t)l * NLR, xlr, NN, NLR, 0);
        k_gat_edge<<<(NN + 1) / 2, 256>>>(xlr, att + (size_t)l * HEADS * HID,
                                          cbias + l * HID, hc, hn, offs, csr);
        float* t = hc; hc = hn; hn = t;
    }

    // predictor MLP (z1/z2 carved out of xlr scratch; z2 padded to width 128)
    float* z1 = xlr;
    float* z2 = xlr + (size_t)NN * HID;
    k_gemm2<128><<<dim3(MB, 1), 256, G2_SMEM>>>(hc, p1_W, p1_b, z1, NN, HID, 1);
    k_gemm2<128><<<dim3(MB, 1), 256, G2_SMEM>>>(z1, p2p, p2b, z2, NN, 128, 1);
    k_pred3<<<(NN * 32 + 255) / 256, 256>>>(z2, p3_W, p3_b, out, NN);
}

// round 7
// speedup vs baseline: 1.3032x; 1.1065x over previous
#include <cuda_runtime.h>
#include <math.h>
#include <stdint.h>

#define NN   50000
#define EE   800000
#define FIN  64
#define HID  128
#define HEADS 4
#define HOUT 512           // HEADS*HID
#define NLR  1024          // packed xl|xr row width
#define LAYERS 3
#define NEG_SLOPE 0.2f
#define SCAN_B 1024
#define NBLK ((NN + SCAN_B - 1) / SCAN_B)   // 49

// B-image geometry: per n-block(128) per k-chunk(32): 4096 words (16KB)
#define IMG_EMB 0                       // nb=1, nc=2  -> 8192 words
#define IMG_WB  8192                    // 3 layers x (nb=8, nc=4) -> 131072 each
#define IMG_P1  (8192 + 3 * 131072)     // nb=1, nc=4 -> 16384
#define IMG_P2  (IMG_P1 + 16384)        // nb=1, nc=4 -> 16384
#define IMG_TOTAL (IMG_P2 + 16384)      // 434176 words

// ---------------- scratch (static device globals; no allocations) ----------------
__device__ float    g_hA[(size_t)NN * HID];
__device__ float    g_hB[(size_t)NN * HID];
__device__ float    g_xlr[(size_t)NN * NLR];
__device__ uint32_t g_img[IMG_TOTAL];
__device__ float    g_bB[(size_t)LAYERS * NLR];
__device__ float    g_p2b[128];
__device__ int      g_deg[NN];
__device__ int      g_offs[NN + 1];
__device__ int      g_cursor[NN];
__device__ int      g_csr[EE];
__device__ int      g_blksum[NBLK];
__device__ int      g_blkoff[NBLK];

__device__ __forceinline__ uint32_t f2tf(float f) {
    uint32_t u;
    asm("cvt.rna.tf32.f32 %0, %1;" : "=r"(u) : "f"(f));
    return u;
}
__device__ __forceinline__ void mma_tf32(float* d, const uint32_t* a, const uint32_t* b) {
    asm volatile(
        "mma.sync.aligned.m16n8k8.row.col.f32.tf32.tf32.f32 "
        "{%0,%1,%2,%3}, {%4,%5,%6,%7}, {%8,%9}, {%0,%1,%2,%3};"
        : "+f"(d[0]), "+f"(d[1]), "+f"(d[2]), "+f"(d[3])
        : "r"(a[0]), "r"(a[1]), "r"(a[2]), "r"(a[3]), "r"(b[0]), "r"(b[1]));
}
__device__ __forceinline__ uint32_t smem_u32(const void* p) {
    uint32_t a;
    asm("{ .reg .u64 t; cvta.to.shared.u64 t, %1; cvt.u32.u64 %0, t; }" : "=r"(a) : "l"(p));
    return a;
}

// ---------------- prep: build B fragment images (pre-converted tf32, pre-swizzled) ----------------
// image word u within a chunk: u = ((g*2 + k8h)*32 + grp*4 + lig)*4 + k8l*2 + slot
//   value = tf32( B[kc*32 + (k8h*2+k8l)*8 + lig + slot*4][blk*128 + g*8 + grp] )
__global__ void k_img(const float* __restrict__ emb_W, const float* __restrict__ Wl,
                      const float* __restrict__ Wr, const float* __restrict__ p1_W,
                      const float* __restrict__ p2_W, uint32_t* __restrict__ img) {
    int w = blockIdx.x * blockDim.x + threadIdx.x;
    if (w >= IMG_TOTAL) return;
    int rem, nc, seg;
    if (w < IMG_WB)           { seg = 0; rem = w;            nc = 2; }
    else if (w < IMG_P1)      { seg = 1; rem = w - IMG_WB;   nc = 4; }
    else if (w < IMG_P2)      { seg = 2; rem = w - IMG_P1;   nc = 4; }
    else                      { seg = 3; rem = w - IMG_P2;   nc = 4; }
    int layer = 0;
    if (seg == 1) { layer = rem / 131072; rem %= 131072; }
    int cw = nc * 4096;
    int blk = rem / cw;
    int r2 = rem % cw;
    int kc = r2 / 4096;
    int u = r2 % 4096;
    int slot = u & 1, k8l = (u >> 1) & 1;
    int lane = (u >> 2) & 31;
    int lig = lane & 3, grp = lane >> 2;
    int gk = u >> 7;
    int k8h = gk & 1, g = gk >> 1;
    int k = kc * 32 + (k8h * 2 + k8l) * 8 + lig + slot * 4;
    int n = blk * 128 + g * 8 + grp;
    float val;
    if (seg == 0) {
        val = emb_W[k * HID + n];                       // [64][128]
    } else if (seg == 1) {
        val = (n < HOUT) ? Wl[((size_t)layer * HID + k) * HOUT + n]
                         : Wr[((size_t)layer * HID + k) * HOUT + (n - HOUT)];
    } else if (seg == 2) {
        val = p1_W[k * HID + n];                        // [128][128]
    } else {
        val = (n < 64) ? p2_W[k * 64 + n] : 0.f;        // [128][64] padded
    }
    img[w] = f2tf(val);
}

__global__ void k_bias(const float* __restrict__ bl, const float* __restrict__ br,
                       const float* __restrict__ p2_b,
                       float* __restrict__ bB, float* __restrict__ p2bp) {
    int i = blockIdx.x * blockDim.x + threadIdx.x;
    if (i < LAYERS * NLR) {
        int l = i / NLR, n = i % NLR;
        bB[i] = (n < HOUT) ? bl[l * HOUT + n] : br[l * HOUT + n - HOUT];
    }
    if (i < 128) p2bp[i] = (i < 64) ? p2_b[i] : 0.f;
}

// ---------------- CSR build ----------------
__global__ void k_zero_int(int* p, int n) {
    int i = blockIdx.x * blockDim.x + threadIdx.x;
    if (i < n) p[i] = 0;
}
__global__ void k_count_deg(const int* __restrict__ dst, int* __restrict__ deg, int e) {
    int i = blockIdx.x * blockDim.x + threadIdx.x;
    if (i < e) atomicAdd(&deg[dst[i]], 1);
}
__global__ void k_scan_part(const int* __restrict__ deg, int* __restrict__ offs,
                            int* __restrict__ blksum, int n) {
    __shared__ int wsum[32];
    int gid = blockIdx.x * SCAN_B + threadIdx.x;
    int lane = threadIdx.x & 31, wid = threadIdx.x >> 5;
    int v = (gid < n) ? deg[gid] : 0;
    int s = v;
    #pragma unroll
    for (int o = 1; o < 32; o <<= 1) {
        int t = __shfl_up_sync(0xffffffffu, s, o);
        if (lane >= o) s += t;
    }
    if (lane == 31) wsum[wid] = s;
    __syncthreads();
    if (wid == 0) {
        int ws = wsum[lane];
        #pragma unroll
        for (int o = 1; o < 32; o <<= 1) {
            int t = __shfl_up_sync(0xffffffffu, ws, o);
            if (lane >= o) ws += t;
        }
        wsum[lane] = ws;
    }
    __syncthreads();
    int base = wid ? wsum[wid - 1] : 0;
    int incl = base + s;
    if (gid < n) offs[gid] = incl - v;
    if (threadIdx.x == SCAN_B - 1) blksum[blockIdx.x] = incl;
}
__global__ void k_scan_blk(const int* __restrict__ blksum, int* __restrict__ blkoff,
                           int* __restrict__ offs, int nblk, int n) {
    __shared__ int sm[64];
    int t = threadIdx.x;
    int v = (t < nblk) ? blksum[t] : 0;
    sm[t] = v;
    __syncthreads();
    #pragma unroll
    for (int d = 1; d < 64; d <<= 1) {
        int tv = (t >= d) ? sm[t - d] : 0;
        __syncthreads();
        sm[t] += tv;
        __syncthreads();
    }
    if (t < nblk) blkoff[t] = sm[t] - v;
    if (t == 63) offs[n] = sm[63];
}
__global__ void k_scan_add(int* __restrict__ offs, const int* __restrict__ blkoff,
                           int* __restrict__ cursor, int n) {
    int gid = blockIdx.x * SCAN_B + threadIdx.x;
    if (gid < n) {
        int o = offs[gid] + blkoff[blockIdx.x];
        offs[gid] = o;
        cursor[gid] = o;
    }
}
__global__ void k_fill_csr(const int* __restrict__ src, const int* __restrict__ dst,
                           int* __restrict__ cursor, int* __restrict__ csr, int e) {
    int i = blockIdx.x * blockDim.x + threadIdx.x;
    if (i < e) {
        int p = atomicAdd(&cursor[dst[i]], 1);
        csr[p] = src[i];
    }
}

// ---------------- GEMM v3: 4 warps of 64x64, cp.async staging, B fragment image ----------------
// Block 128x128. A raw fp32 in smem (XOR-swizzled rows), cvt to tf32 after LDS.
// smem per buffer: A 4096 words + B 4096 words = 32KB; 2 buffers = 64KB.
#define G3_SMEM 65536

template <int KT>
__global__ __launch_bounds__(128, 2) void k_gemm3(
    const float* __restrict__ A, const uint32_t* __restrict__ img,
    const float* __restrict__ bias, float* __restrict__ C,
    int M, int Ns, int relu) {
    extern __shared__ uint32_t sm[];
    constexpr int NK = KT / 32;
    int tid = threadIdx.x;
    int wid = tid >> 5, lane = tid & 31;
    int grp = lane >> 2, lig = lane & 3;
    const int wm = (wid & 1) * 64;
    const int wg8 = (wid >> 1) * 8;       // warp fragment-col base (g index)
    const int bm = blockIdx.x * 128, bn = blockIdx.y * 128;
    const uint32_t* imgB = img + (size_t)blockIdx.y * NK * 4096;
    uint32_t sbase = smem_u32(sm);

    const int ar = tid >> 3;              // A stage row (+16*i)
    const int aseg = (tid & 7) * 4;       // A stage col (words)

    float acc[4][8][4];
    #pragma unroll
    for (int i = 0; i < 4; i++)
        #pragma unroll
        for (int j = 0; j < 8; j++)
            #pragma unroll
            for (int q = 0; q < 4; q++) acc[i][j][q] = 0.f;

    auto stage = [&](int kc, int b) {
        uint32_t abase = sbase + b * 32768;
        #pragma unroll
        for (int i = 0; i < 8; i++) {
            int r = ar + i * 16;
            int gr = bm + r;
            uint32_t dst = abase + (uint32_t)(r * 32 + (aseg ^ ((r & 7) << 2))) * 4;
            const float* src = A + (size_t)gr * KT + kc * 32 + aseg;
            int sz = (gr < M) ? 16 : 0;
            asm volatile("cp.async.cg.shared.global [%0], [%1], 16, %2;"
                         :: "r"(dst), "l"(src), "r"(sz));
        }
        uint32_t bbase = abase + 16384;
        const uint32_t* bsrc = imgB + kc * 4096 + tid * 4;
        #pragma unroll
        for (int i = 0; i < 8; i++) {
            uint32_t dst = bbase + (uint32_t)(tid * 4 + i * 512) * 4;
            asm volatile("cp.async.cg.shared.global [%0], [%1], 16, 16;"
                         :: "r"(dst), "l"(bsrc + i * 512));
        }
        asm volatile("cp.async.commit_group;");
    };

    stage(0, 0);
    int buf = 0;
    #pragma unroll
    for (int kc = 0; kc < NK; kc++) {
        asm volatile("cp.async.wait_group 0;");
        __syncthreads();
        if (kc + 1 < NK) stage(kc + 1, buf ^ 1);

        const uint32_t* As = sm + buf * 8192;
        const uint32_t* Bs = As + 4096;
        #pragma unroll
        for (int k8h = 0; k8h < 2; k8h++) {
            uint4 bq[8];
            #pragma unroll
            for (int nt = 0; nt < 8; nt++)
                bq[nt] = *(const uint4*)(Bs + (((wg8 + nt) * 2 + k8h) * 32 + lane) * 4);
            #pragma unroll
            for (int k8l = 0; k8l < 2; k8l++) {
                int c0 = (k8h * 2 + k8l) * 8 + lig;
                int sw = grp << 2;
                #pragma unroll
                for (int mt = 0; mt < 4; mt++) {
                    int r0 = wm + mt * 16 + grp;
                    uint32_t av[4];
                    av[0] = f2tf(__uint_as_float(As[r0 * 32 + (c0 ^ sw)]));
                    av[1] = f2tf(__uint_as_float(As[(r0 + 8) * 32 + (c0 ^ sw)]));
                    av[2] = f2tf(__uint_as_float(As[r0 * 32 + ((c0 + 4) ^ sw)]));
                    av[3] = f2tf(__uint_as_float(As[(r0 + 8) * 32 + ((c0 + 4) ^ sw)]));
                    #pragma unroll
                    for (int nt = 0; nt < 8; nt++) {
                        uint32_t bv[2];
                        if (k8l == 0) { bv[0] = bq[nt].x; bv[1] = bq[nt].y; }
                        else          { bv[0] = bq[nt].z; bv[1] = bq[nt].w; }
                        mma_tf32(acc[mt][nt], av, bv);
                    }
                }
            }
        }
        buf ^= 1;
    }

    // epilogue
    #pragma unroll
    for (int mt = 0; mt < 4; mt++) {
        #pragma unroll
        for (int nt = 0; nt < 8; nt++) {
            int col = bn + (wg8 + nt) * 8 + lig * 2;
            float b0 = __ldg(bias + col), b1 = __ldg(bias + col + 1);
            int row0 = bm + wm + mt * 16 + grp;
            if (row0 < M) {
                float v0 = acc[mt][nt][0] + b0;
                float v1 = acc[mt][nt][1] + b1;
                if (relu) { v0 = fmaxf(v0, 0.f); v1 = fmaxf(v1, 0.f); }
                *(float2*)(C + (size_t)row0 * Ns + col) = make_float2(v0, v1);
            }
            int row1 = row0 + 8;
            if (row1 < M) {
                float v2 = acc[mt][nt][2] + b0;
                float v3 = acc[mt][nt][3] + b1;
                if (relu) { v2 = fmaxf(v2, 0.f); v3 = fmaxf(v3, 0.f); }
                *(float2*)(C + (size_t)row1 * Ns + col) = make_float2(v2, v3);
            }
        }
    }
}

// ---------------- GATv2 edge kernel: pair-unrolled online softmax ----------------
__device__ __forceinline__ float leaky_dot(const float4 av, const float4 v, const float4 xrv) {
    float m0 = v.x + xrv.x; m0 = m0 > 0.f ? m0 : NEG_SLOPE * m0;
    float m1 = v.y + xrv.y; m1 = m1 > 0.f ? m1 : NEG_SLOPE * m1;
    float m2 = v.z + xrv.z; m2 = m2 > 0.f ? m2 : NEG_SLOPE * m2;
    float m3 = v.w + xrv.w; m3 = m3 > 0.f ? m3 : NEG_SLOPE * m3;
    return av.x * m0 + av.y * m1 + av.z * m2 + av.w * m3;
}

__global__ __launch_bounds__(256) void k_gat_edge(
    const float* __restrict__ xlr, const float* __restrict__ att,
    const float* __restrict__ cbias,
    const float* __restrict__ hin, float* __restrict__ hout,
    const int* __restrict__ offs, const int* __restrict__ csr) {
    int half = threadIdx.x >> 7;
    int node = blockIdx.x * 2 + half;
    int t128 = threadIdx.x & 127;
    int w = t128 >> 5, lane = threadIdx.x & 31;
    __shared__ float hacc[2][HEADS][HID];

    if (node < NN) {
        int beg = offs[node], end = offs[node + 1];
        const size_t off = (size_t)w * HID + lane * 4;
        const float4 xrv = *(const float4*)(xlr + (size_t)node * NLR + HOUT + off);
        const float4 av  = *(const float4*)(att + w * HID + lane * 4);

        float emax = -1e30f, denom = 0.f;
        float4 acc = make_float4(0.f, 0.f, 0.f, 0.f);
        int i = beg;
        for (; i + 1 < end; i += 2) {
            int s0 = __ldg(csr + i), s1 = __ldg(csr + i + 1);
            float4 v0 = *(const float4*)(xlr + (size_t)s0 * NLR + off);
            float4 v1 = *(const float4*)(xlr + (size_t)s1 * NLR + off);
            float p0 = leaky_dot(av, v0, xrv);
            float p1 = leaky_dot(av, v1, xrv);
            #pragma unroll
            for (int o = 16; o; o >>= 1) {
                p0 += __shfl_xor_sync(0xffffffffu, p0, o);
                p1 += __shfl_xor_sync(0xffffffffu, p1, o);
            }
            float nm = fmaxf(emax, fmaxf(p0, p1));
            float sc = __expf(emax - nm);
            denom *= sc;
            acc.x *= sc; acc.y *= sc; acc.z *= sc; acc.w *= sc;
            emax = nm;
            float w0 = __expf(p0 - nm), w1 = __expf(p1 - nm);
            denom += w0 + w1;
            acc.x += w0 * v0.x + w1 * v1.x;
            acc.y += w0 * v0.y + w1 * v1.y;
            acc.z += w0 * v0.z + w1 * v1.z;
            acc.w += w0 * v0.w + w1 * v1.w;
        }
        if (i < end) {
            int s0 = __ldg(csr + i);
            float4 v0 = *(const float4*)(xlr + (size_t)s0 * NLR + off);
            float p0 = leaky_dot(av, v0, xrv);
            #pragma unroll
            for (int o = 16; o; o >>= 1) p0 += __shfl_xor_sync(0xffffffffu, p0, o);
            float nm = fmaxf(emax, p0);
            float sc = __expf(emax - nm);
            denom *= sc;
            acc.x *= sc; acc.y *= sc; acc.z *= sc; acc.w *= sc;
            emax = nm;
            float w0 = __expf(p0 - nm);
            denom += w0;
            acc.x += w0 * v0.x; acc.y += w0 * v0.y;
            acc.z += w0 * v0.z; acc.w += w0 * v0.w;
        }
        float inv = denom > 0.f ? 1.f / denom : 0.f;
        hacc[half][w][lane * 4 + 0] = acc.x * inv;
        hacc[half][w][lane * 4 + 1] = acc.y * inv;
        hacc[half][w][lane * 4 + 2] = acc.z * inv;
        hacc[half][w][lane * 4 + 3] = acc.w * inv;
    }
    __syncthreads();
    if (node < NN) {
        float sv = (hacc[half][0][t128] + hacc[half][1][t128] +
                    hacc[half][2][t128] + hacc[half][3][t128]) * 0.25f
                 + cbias[t128] + hin[(size_t)node * HID + t128];
        hout[(size_t)node * HID + t128] = fmaxf(sv, 0.f);
    }
}

// ---------------- final predictor head (z2 row stride 128) ----------------
__global__ void k_pred3(const float* __restrict__ z2, const float* __restrict__ W,
                        const float* __restrict__ b, float* __restrict__ out, int n) {
    int warp = (blockIdx.x * blockDim.x + threadIdx.x) >> 5;
    int lane = threadIdx.x & 31;
    if (warp >= n) return;
    const float* zr = z2 + (size_t)warp * 128;
    float p = zr[lane] * W[lane] + zr[lane + 32] * W[lane + 32];
    #pragma unroll
    for (int o = 16; o; o >>= 1) p += __shfl_xor_sync(0xffffffffu, p, o);
    if (lane == 0) {
        float s = p + b[0];
        s = fminf(fmaxf(s, -15.f), 15.f);
        out[warp] = s;
    }
}

// ---------------- launch ----------------
extern "C" void kernel_launch(void* const* d_in, const int* in_sizes, int n_in,
                              void* d_out, int out_size) {
    const float* x      = (const float*)d_in[0];
    const int*   eidx   = (const int*)d_in[1];
    const float* emb_W  = (const float*)d_in[3];
    const float* emb_b  = (const float*)d_in[4];
    const float* Wl     = (const float*)d_in[5];
    const float* bl     = (const float*)d_in[6];
    const float* Wr     = (const float*)d_in[7];
    const float* br     = (const float*)d_in[8];
    const float* att    = (const float*)d_in[9];
    const float* cbias  = (const float*)d_in[10];
    const float* p1_W   = (const float*)d_in[11];
    const float* p1_b   = (const float*)d_in[12];
    const float* p2_W   = (const float*)d_in[13];
    const float* p2_b   = (const float*)d_in[14];
    const float* p3_W   = (const float*)d_in[15];
    const float* p3_b   = (const float*)d_in[16];
    float* out = (float*)d_out;

    const int* srcp = eidx;
    const int* dstp = eidx + EE;

    float *hA, *hB, *xlr, *bB, *p2b;
    uint32_t* img;
    int *deg, *offs, *cursor, *csr, *blksum, *blkoff;
    cudaGetSymbolAddress((void**)&hA, g_hA);
    cudaGetSymbolAddress((void**)&hB, g_hB);
    cudaGetSymbolAddress((void**)&xlr, g_xlr);
    cudaGetSymbolAddress((void**)&img, g_img);
    cudaGetSymbolAddress((void**)&bB, g_bB);
    cudaGetSymbolAddress((void**)&p2b, g_p2b);
    cudaGetSymbolAddress((void**)&deg, g_deg);
    cudaGetSymbolAddress((void**)&offs, g_offs);
    cudaGetSymbolAddress((void**)&cursor, g_cursor);
    cudaGetSymbolAddress((void**)&csr, g_csr);
    cudaGetSymbolAddress((void**)&blksum, g_blksum);
    cudaGetSymbolAddress((void**)&blkoff, g_blkoff);

    cudaFuncSetAttribute(k_gemm3<64>,  cudaFuncAttributeMaxDynamicSharedMemorySize, G3_SMEM);
    cudaFuncSetAttribute(k_gemm3<128>, cudaFuncAttributeMaxDynamicSharedMemorySize, G3_SMEM);

    const int MB = (NN + 127) / 128;  // 391

    // (1) build B fragment images
    k_img<<<(IMG_TOTAL + 255) / 256, 256>>>(emb_W, Wl, Wr, p1_W, p2_W, img);
    // (2) bias packing
    k_bias<<<(LAYERS * NLR + 255) / 256, 256>>>(bl, br, p2_b, bB, p2b);
    // (3) embedding: h = relu(x @ emb_W + emb_b)
    k_gemm3<64><<<dim3(MB, 1), 128, G3_SMEM>>>(x, img + IMG_EMB, emb_b, hA, NN, HID, 1);
    // (4) layer-1 xlr GEMM  <-- profiled slot
    k_gemm3<128><<<dim3(MB, NLR / 128), 128, G3_SMEM>>>(hA, img + IMG_WB, bB, xlr, NN, NLR, 0);
    // CSR build
    k_zero_int<<<(NN + 255) / 256, 256>>>(deg, NN);
    k_count_deg<<<(EE + 255) / 256, 256>>>(dstp, deg, EE);
    k_scan_part<<<NBLK, SCAN_B>>>(deg, offs, blksum, NN);
    k_scan_blk<<<1, 64>>>(blksum, blkoff, offs, NBLK, NN);
    k_scan_add<<<NBLK, SCAN_B>>>(offs, blkoff, cursor, NN);
    k_fill_csr<<<(EE + 255) / 256, 256>>>(srcp, dstp, cursor, csr, EE);

    // layer 1 edge
    float* hc = hA;
    float* hn = hB;
    k_gat_edge<<<(NN + 1) / 2, 256>>>(xlr, att, cbias, hc, hn, offs, csr);
    { float* t = hc; hc = hn; hn = t; }

    // layers 2..3
    for (int l = 1; l < LAYERS; l++) {
        k_gemm3<128><<<dim3(MB, NLR / 128), 128, G3_SMEM>>>(
            hc, img + IMG_WB + (size_t)l * 131072, bB + (size_t)l * NLR, xlr, NN, NLR, 0);
        k_gat_edge<<<(NN + 1) / 2, 256>>>(xlr, att + (size_t)l * HEADS * HID,
                                          cbias + l * HID, hc, hn, offs, csr);
        float* t = hc; hc = hn; hn = t;
    }

    // predictor MLP (z1/z2 carved out of xlr scratch; z2 width 128, cols>=64 zero)
    float* z1 = xlr;
    float* z2 = xlr + (size_t)NN * HID;
    k_gemm3<128><<<dim3(MB, 1), 128, G3_SMEM>>>(hc, img + IMG_P1, p1_b, z1, NN, HID, 1);
    k_gemm3<128><<<dim3(MB, 1), 128, G3_SMEM>>>(z1, img + IMG_P2, p2b, z2, NN, 128, 1);
    k_pred3<<<(NN * 32 + 255) / 256, 256>>>(z2, p3_W, p3_b, out, NN);
}

// round 8
// speedup vs baseline: 1.4157x; 1.0863x over previous
#include <cuda_runtime.h>
#include <cuda_fp16.h>
#include <math.h>
#include <stdint.h>

#define NN   50000
#define EE   800000
#define FIN  64
#define HID  128
#define HEADS 4
#define HOUT 512           // HEADS*HID
#define LAYERS 3
#define NEG_SLOPE 0.2f
#define SCAN_B 1024
#define NBLK ((NN + SCAN_B - 1) / SCAN_B)   // 49

// B-image geometry: per n-block(128) per k-chunk(32): 4096 words (16KB)
#define IMG_EMB 0                       // nb=1, nc=2  -> 8192 words
#define IMG_WB  8192                    // 3 layers x (nb=8, nc=4) -> 131072 each
#define IMG_P1  (8192 + 3 * 131072)     // nb=1, nc=4 -> 16384
#define IMG_P2  (IMG_P1 + 16384)        // nb=1, nc=4 -> 16384
#define IMG_TOTAL (IMG_P2 + 16384)

// ---------------- scratch (static device globals; no allocations) ----------------
__device__ float    g_hA[(size_t)NN * HID];
__device__ float    g_hB[(size_t)NN * HID];
__device__ __half   g_xlh[(size_t)NN * HOUT];   // fp16 xl, row stride 512
__device__ float    g_xr[(size_t)NN * HOUT];    // fp32 xr / predictor scratch, row stride 512
__device__ uint32_t g_img[IMG_TOTAL];
__device__ float    g_bB[(size_t)LAYERS * 1024];
__device__ float    g_p2b[128];
__device__ int      g_deg[NN];
__device__ int      g_offs[NN + 1];
__device__ int      g_cursor[NN];
__device__ int      g_csr[EE];
__device__ int      g_blksum[NBLK];
__device__ int      g_blkoff[NBLK];

__device__ __forceinline__ uint32_t f2tf(float f) {
    uint32_t u;
    asm("cvt.rna.tf32.f32 %0, %1;" : "=r"(u) : "f"(f));
    return u;
}
__device__ __forceinline__ void mma_tf32(float* d, const uint32_t* a, const uint32_t* b) {
    asm volatile(
        "mma.sync.aligned.m16n8k8.row.col.f32.tf32.tf32.f32 "
        "{%0,%1,%2,%3}, {%4,%5,%6,%7}, {%8,%9}, {%0,%1,%2,%3};"
        : "+f"(d[0]), "+f"(d[1]), "+f"(d[2]), "+f"(d[3])
        : "r"(a[0]), "r"(a[1]), "r"(a[2]), "r"(a[3]), "r"(b[0]), "r"(b[1]));
}
__device__ __forceinline__ uint32_t smem_u32(const void* p) {
    uint32_t a;
    asm("{ .reg .u64 t; cvta.to.shared.u64 t, %1; cvt.u32.u64 %0, t; }" : "=r"(a) : "l"(p));
    return a;
}

// ---------------- prep: build B fragment images (pre-converted tf32, pre-swizzled) ----------------
__global__ void k_img(const float* __restrict__ emb_W, const float* __restrict__ Wl,
                      const float* __restrict__ Wr, const float* __restrict__ p1_W,
                      const float* __restrict__ p2_W, uint32_t* __restrict__ img) {
    int w = blockIdx.x * blockDim.x + threadIdx.x;
    if (w >= IMG_TOTAL) return;
    int rem, nc, seg;
    if (w < IMG_WB)           { seg = 0; rem = w;            nc = 2; }
    else if (w < IMG_P1)      { seg = 1; rem = w - IMG_WB;   nc = 4; }
    else if (w < IMG_P2)      { seg = 2; rem = w - IMG_P1;   nc = 4; }
    else                      { seg = 3; rem = w - IMG_P2;   nc = 4; }
    int layer = 0;
    if (seg == 1) { layer = rem / 131072; rem %= 131072; }
    int cw = nc * 4096;
    int blk = rem / cw;
    int r2 = rem % cw;
    int kc = r2 / 4096;
    int u = r2 % 4096;
    int slot = u & 1, k8l = (u >> 1) & 1;
    int lane = (u >> 2) & 31;
    int lig = lane & 3, grp = lane >> 2;
    int gk = u >> 7;
    int k8h = gk & 1, g = gk >> 1;
    int k = kc * 32 + (k8h * 2 + k8l) * 8 + lig + slot * 4;
    int n = blk * 128 + g * 8 + grp;
    float val;
    if (seg == 0) {
        val = emb_W[k * HID + n];
    } else if (seg == 1) {
        val = (n < HOUT) ? Wl[((size_t)layer * HID + k) * HOUT + n]
                         : Wr[((size_t)layer * HID + k) * HOUT + (n - HOUT)];
    } else if (seg == 2) {
        val = p1_W[k * HID + n];
    } else {
        val = (n < 64) ? p2_W[k * 64 + n] : 0.f;
    }
    img[w] = f2tf(val);
}

__global__ void k_bias(const float* __restrict__ bl, const float* __restrict__ br,
                       const float* __restrict__ p2_b,
                       float* __restrict__ bB, float* __restrict__ p2bp) {
    int i = blockIdx.x * blockDim.x + threadIdx.x;
    if (i < LAYERS * 1024) {
        int l = i / 1024, n = i % 1024;
        bB[i] = (n < HOUT) ? bl[l * HOUT + n] : br[l * HOUT + n - HOUT];
    }
    if (i < 128) p2bp[i] = (i < 64) ? p2_b[i] : 0.f;
}

// ---------------- CSR build ----------------
__global__ void k_zero_int(int* p, int n) {
    int i = blockIdx.x * blockDim.x + threadIdx.x;
    if (i < n) p[i] = 0;
}
__global__ void k_count_deg(const int* __restrict__ dst, int* __restrict__ deg, int e) {
    int i = blockIdx.x * blockDim.x + threadIdx.x;
    if (i < e) atomicAdd(&deg[dst[i]], 1);
}
__global__ void k_scan_part(const int* __restrict__ deg, int* __restrict__ offs,
                            int* __restrict__ blksum, int n) {
    __shared__ int wsum[32];
    int gid = blockIdx.x * SCAN_B + threadIdx.x;
    int lane = threadIdx.x & 31, wid = threadIdx.x >> 5;
    int v = (gid < n) ? deg[gid] : 0;
    int s = v;
    #pragma unroll
    for (int o = 1; o < 32; o <<= 1) {
        int t = __shfl_up_sync(0xffffffffu, s, o);
        if (lane >= o) s += t;
    }
    if (lane == 31) wsum[wid] = s;
    __syncthreads();
    if (wid == 0) {
        int ws = wsum[lane];
        #pragma unroll
        for (int o = 1; o < 32; o <<= 1) {
            int t = __shfl_up_sync(0xffffffffu, ws, o);
            if (lane >= o) ws += t;
        }
        wsum[lane] = ws;
    }
    __syncthreads();
    int base = wid ? wsum[wid - 1] : 0;
    int incl = base + s;
    if (gid < n) offs[gid] = incl - v;
    if (threadIdx.x == SCAN_B - 1) blksum[blockIdx.x] = incl;
}
__global__ void k_scan_blk(const int* __restrict__ blksum, int* __restrict__ blkoff,
                           int* __restrict__ offs, int nblk, int n) {
    __shared__ int sm[64];
    int t = threadIdx.x;
    int v = (t < nblk) ? blksum[t] : 0;
    sm[t] = v;
    __syncthreads();
    #pragma unroll
    for (int d = 1; d < 64; d <<= 1) {
        int tv = (t >= d) ? sm[t - d] : 0;
        __syncthreads();
        sm[t] += tv;
        __syncthreads();
    }
    if (t < nblk) blkoff[t] = sm[t] - v;
    if (t == 63) offs[n] = sm[63];
}
__global__ void k_scan_add(int* __restrict__ offs, const int* __restrict__ blkoff,
                           int* __restrict__ cursor, int n) {
    int gid = blockIdx.x * SCAN_B + threadIdx.x;
    if (gid < n) {
        int o = offs[gid] + blkoff[blockIdx.x];
        offs[gid] = o;
        cursor[gid] = o;
    }
}
__global__ void k_fill_csr(const int* __restrict__ src, const int* __restrict__ dst,
                           int* __restrict__ cursor, int* __restrict__ csr, int e) {
    int i = blockIdx.x * blockDim.x + threadIdx.x;
    if (i < e) {
        int p = atomicAdd(&cursor[dst[i]], 1);
        csr[p] = src[i];
    }
}

// ---------------- GEMM v3: 4 warps of 64x64, cp.async staging, B fragment image ----------------
// MODE 0: fp32 C[M,Ns]. MODE 1: split output — cols<512 -> fp16 Ch (stride 512),
// cols>=512 -> fp32 C (stride 512, col-512). Branch is uniform per blockIdx.y.
#define G3_SMEM 65536

template <int KT, int MODE>
__global__ __launch_bounds__(128, 2) void k_gemm3(
    const float* __restrict__ A, const uint32_t* __restrict__ img,
    const float* __restrict__ bias, float* __restrict__ C, __half* __restrict__ Ch,
    int M, int Ns, int relu) {
    extern __shared__ uint32_t sm[];
    constexpr int NK = KT / 32;
    int tid = threadIdx.x;
    int wid = tid >> 5, lane = tid & 31;
    int grp = lane >> 2, lig = lane & 3;
    const int wm = (wid & 1) * 64;
    const int wg8 = (wid >> 1) * 8;
    const int bm = blockIdx.x * 128, bn = blockIdx.y * 128;
    const uint32_t* imgB = img + (size_t)blockIdx.y * NK * 4096;
    uint32_t sbase = smem_u32(sm);

    const int ar = tid >> 3;
    const int aseg = (tid & 7) * 4;

    float acc[4][8][4];
    #pragma unroll
    for (int i = 0; i < 4; i++)
        #pragma unroll
        for (int j = 0; j < 8; j++)
            #pragma unroll
            for (int q = 0; q < 4; q++) acc[i][j][q] = 0.f;

    auto stage = [&](int kc, int b) {
        uint32_t abase = sbase + b * 32768;
        #pragma unroll
        for (int i = 0; i < 8; i++) {
            int r = ar + i * 16;
            int gr = bm + r;
            uint32_t dst = abase + (uint32_t)(r * 32 + (aseg ^ ((r & 7) << 2))) * 4;
            const float* src = A + (size_t)gr * KT + kc * 32 + aseg;
            int sz = (gr < M) ? 16 : 0;
            asm volatile("cp.async.cg.shared.global [%0], [%1], 16, %2;"
                         :: "r"(dst), "l"(src), "r"(sz));
        }
        uint32_t bbase = abase + 16384;
        const uint32_t* bsrc = imgB + kc * 4096 + tid * 4;
        #pragma unroll
        for (int i = 0; i < 8; i++) {
            uint32_t dst = bbase + (uint32_t)(tid * 4 + i * 512) * 4;
            asm volatile("cp.async.cg.shared.global [%0], [%1], 16, 16;"
                         :: "r"(dst), "l"(bsrc + i * 512));
        }
        asm volatile("cp.async.commit_group;");
    };

    stage(0, 0);
    int buf = 0;
    #pragma unroll
    for (int kc = 0; kc < NK; kc++) {
        asm volatile("cp.async.wait_group 0;");
        __syncthreads();
        if (kc + 1 < NK) stage(kc + 1, buf ^ 1);

        const uint32_t* As = sm + buf * 8192;
        const uint32_t* Bs = As + 4096;
        #pragma unroll
        for (int k8h = 0; k8h < 2; k8h++) {
            uint4 bq[8];
            #pragma unroll
            for (int nt = 0; nt < 8; nt++)
                bq[nt] = *(const uint4*)(Bs + (((wg8 + nt) * 2 + k8h) * 32 + lane) * 4);
            #pragma unroll
            for (int k8l = 0; k8l < 2; k8l++) {
                int c0 = (k8h * 2 + k8l) * 8 + lig;
                int sw = grp << 2;
                #pragma unroll
                for (int mt = 0; mt < 4; mt++) {
                    int r0 = wm + mt * 16 + grp;
                    uint32_t av[4];
                    av[0] = f2tf(__uint_as_float(As[r0 * 32 + (c0 ^ sw)]));
                    av[1] = f2tf(__uint_as_float(As[(r0 + 8) * 32 + (c0 ^ sw)]));
                    av[2] = f2tf(__uint_as_float(As[r0 * 32 + ((c0 + 4) ^ sw)]));
                    av[3] = f2tf(__uint_as_float(As[(r0 + 8) * 32 + ((c0 + 4) ^ sw)]));
                    #pragma unroll
                    for (int nt = 0; nt < 8; nt++) {
                        uint32_t bv[2];
                        if (k8l == 0) { bv[0] = bq[nt].x; bv[1] = bq[nt].y; }
                        else          { bv[0] = bq[nt].z; bv[1] = bq[nt].w; }
                        mma_tf32(acc[mt][nt], av, bv);
                    }
                }
            }
        }
        buf ^= 1;
    }

    // epilogue
    #pragma unroll
    for (int mt = 0; mt < 4; mt++) {
        #pragma unroll
        for (int nt = 0; nt < 8; nt++) {
            int col = bn + (wg8 + nt) * 8 + lig * 2;
            float b0 = __ldg(bias + col), b1 = __ldg(bias + col + 1);
            int row0 = bm + wm + mt * 16 + grp;
            int row1 = row0 + 8;
            float v0 = acc[mt][nt][0] + b0;
            float v1 = acc[mt][nt][1] + b1;
            float v2 = acc[mt][nt][2] + b0;
            float v3 = acc[mt][nt][3] + b1;
            if (relu) {
                v0 = fmaxf(v0, 0.f); v1 = fmaxf(v1, 0.f);
                v2 = fmaxf(v2, 0.f); v3 = fmaxf(v3, 0.f);
            }
            if (MODE == 0) {
                if (row0 < M) *(float2*)(C + (size_t)row0 * Ns + col) = make_float2(v0, v1);
                if (row1 < M) *(float2*)(C + (size_t)row1 * Ns + col) = make_float2(v2, v3);
            } else {
                if (col < HOUT) {   // xl -> fp16 (uniform per blockIdx.y)
                    if (row0 < M) *(__half2*)(Ch + (size_t)row0 * HOUT + col) = __floats2half2_rn(v0, v1);
                    if (row1 < M) *(__half2*)(Ch + (size_t)row1 * HOUT + col) = __floats2half2_rn(v2, v3);
                } else {            // xr -> fp32
                    int c2 = col - HOUT;
                    if (row0 < M) *(float2*)(C + (size_t)row0 * HOUT + c2) = make_float2(v0, v1);
                    if (row1 < M) *(float2*)(C + (size_t)row1 * HOUT + c2) = make_float2(v2, v3);
                }
            }
        }
    }
}

// ---------------- GATv2 edge kernel: fp16 xl gathers, pair-unrolled online softmax ----------------
__device__ __forceinline__ float4 ld_xl(const __half* __restrict__ xlh, int s, int off) {
    uint2 raw = *(const uint2*)(xlh + (size_t)s * HOUT + off);
    float2 f01 = __half22float2(*(__half2*)&raw.x);
    float2 f23 = __half22float2(*(__half2*)&raw.y);
    return make_float4(f01.x, f01.y, f23.x, f23.y);
}
__device__ __forceinline__ float leaky_dot(const float4 av, const float4 v, const float4 xrv) {
    float m0 = v.x + xrv.x; m0 = m0 > 0.f ? m0 : NEG_SLOPE * m0;
    float m1 = v.y + xrv.y; m1 = m1 > 0.f ? m1 : NEG_SLOPE * m1;
    float m2 = v.z + xrv.z; m2 = m2 > 0.f ? m2 : NEG_SLOPE * m2;
    float m3 = v.w + xrv.w; m3 = m3 > 0.f ? m3 : NEG_SLOPE * m3;
    return av.x * m0 + av.y * m1 + av.z * m2 + av.w * m3;
}

__global__ __launch_bounds__(256) void k_gat_edge(
    const __half* __restrict__ xlh, const float* __restrict__ xr,
    const float* __restrict__ att, const float* __restrict__ cbias,
    const float* __restrict__ hin, float* __restrict__ hout,
    const int* __restrict__ offs, const int* __restrict__ csr) {
    int half_ = threadIdx.x >> 7;
    int node = blockIdx.x * 2 + half_;
    int t128 = threadIdx.x & 127;
    int w = t128 >> 5, lane = threadIdx.x & 31;
    __shared__ float hacc[2][HEADS][HID];

    if (node < NN) {
        int beg = offs[node], end = offs[node + 1];
        const int off = w * HID + lane * 4;
        const float4 xrv = *(const float4*)(xr + (size_t)node * HOUT + off);
        const float4 av  = *(const float4*)(att + w * HID + lane * 4);

        float emax = -1e30f, denom = 0.f;
        float4 acc = make_float4(0.f, 0.f, 0.f, 0.f);
        int i = beg;
        for (; i + 1 < end; i += 2) {
            int s0 = __ldg(csr + i), s1 = __ldg(csr + i + 1);
            float4 v0 = ld_xl(xlh, s0, off);
            float4 v1 = ld_xl(xlh, s1, off);
            float p0 = leaky_dot(av, v0, xrv);
            float p1 = leaky_dot(av, v1, xrv);
            #pragma unroll
            for (int o = 16; o; o >>= 1) {
                p0 += __shfl_xor_sync(0xffffffffu, p0, o);
                p1 += __shfl_xor_sync(0xffffffffu, p1, o);
            }
            float nm = fmaxf(emax, fmaxf(p0, p1));
            float sc = __expf(emax - nm);
            denom *= sc;
            acc.x *= sc; acc.y *= sc; acc.z *= sc; acc.w *= sc;
            emax = nm;
            float w0 = __expf(p0 - nm), w1 = __expf(p1 - nm);
            denom += w0 + w1;
            acc.x += w0 * v0.x + w1 * v1.x;
            acc.y += w0 * v0.y + w1 * v1.y;
            acc.z += w0 * v0.z + w1 * v1.z;
            acc.w += w0 * v0.w + w1 * v1.w;
        }
        if (i < end) {
            int s0 = __ldg(csr + i);
            float4 v0 = ld_xl(xlh, s0, off);
            float p0 = leaky_dot(av, v0, xrv);
            #pragma unroll
            for (int o = 16; o; o >>= 1) p0 += __shfl_xor_sync(0xffffffffu, p0, o);
            float nm = fmaxf(emax, p0);
            float sc = __expf(emax - nm);
            denom *= sc;
            acc.x *= sc; acc.y *= sc; acc.z *= sc; acc.w *= sc;
            emax = nm;
            float w0 = __expf(p0 - nm);
            denom += w0;
            acc.x += w0 * v0.x; acc.y += w0 * v0.y;
            acc.z += w0 * v0.z; acc.w += w0 * v0.w;
        }
        float inv = denom > 0.f ? 1.f / denom : 0.f;
        hacc[half_][w][lane * 4 + 0] = acc.x * inv;
        hacc[half_][w][lane * 4 + 1] = acc.y * inv;
        hacc[half_][w][lane * 4 + 2] = acc.z * inv;
        hacc[half_][w][lane * 4 + 3] = acc.w * inv;
    }
    __syncthreads();
    if (node < NN) {
        float sv = (hacc[half_][0][t128] + hacc[half_][1][t128] +
                    hacc[half_][2][t128] + hacc[half_][3][t128]) * 0.25f
                 + cbias[t128] + hin[(size_t)node * HID + t128];
        hout[(size_t)node * HID + t128] = fmaxf(sv, 0.f);
    }
}

// ---------------- final predictor head (z2 row stride 128) ----------------
__global__ void k_pred3(const float* __restrict__ z2, const float* __restrict__ W,
                        const float* __restrict__ b, float* __restrict__ out, int n) {
    int warp = (blockIdx.x * blockDim.x + threadIdx.x) >> 5;
    int lane = threadIdx.x & 31;
    if (warp >= n) return;
    const float* zr = z2 + (size_t)warp * 128;
    float p = zr[lane] * W[lane] + zr[lane + 32] * W[lane + 32];
    #pragma unroll
    for (int o = 16; o; o >>= 1) p += __shfl_xor_sync(0xffffffffu, p, o);
    if (lane == 0) {
        float s = p + b[0];
        s = fminf(fmaxf(s, -15.f), 15.f);
        out[warp] = s;
    }
}

// ---------------- launch ----------------
extern "C" void kernel_launch(void* const* d_in, const int* in_sizes, int n_in,
                              void* d_out, int out_size) {
    const float* x      = (const float*)d_in[0];
    const int*   eidx   = (const int*)d_in[1];
    const float* emb_W  = (const float*)d_in[3];
    const float* emb_b  = (const float*)d_in[4];
    const float* Wl     = (const float*)d_in[5];
    const float* bl     = (const float*)d_in[6];
    const float* Wr     = (const float*)d_in[7];
    const float* br     = (const float*)d_in[8];
    const float* att    = (const float*)d_in[9];
    const float* cbias  = (const float*)d_in[10];
    const float* p1_W   = (const float*)d_in[11];
    const float* p1_b   = (const float*)d_in[12];
    const float* p2_W   = (const float*)d_in[13];
    const float* p2_b   = (const float*)d_in[14];
    const float* p3_W   = (const float*)d_in[15];
    const float* p3_b   = (const float*)d_in[16];
    float* out = (float*)d_out;

    const int* srcp = eidx;
    const int* dstp = eidx + EE;

    float *hA, *hB, *xr, *bB, *p2b;
    __half* xlh;
    uint32_t* img;
    int *deg, *offs, *cursor, *csr, *blksum, *blkoff;
    cudaGetSymbolAddress((void**)&hA, g_hA);
    cudaGetSymbolAddress((void**)&hB, g_hB);
    cudaGetSymbolAddress((void**)&xlh, g_xlh);
    cudaGetSymbolAddress((void**)&xr, g_xr);
    cudaGetSymbolAddress((void**)&img, g_img);
    cudaGetSymbolAddress((void**)&bB, g_bB);
    cudaGetSymbolAddress((void**)&p2b, g_p2b);
    cudaGetSymbolAddress((void**)&deg, g_deg);
    cudaGetSymbolAddress((void**)&offs, g_offs);
    cudaGetSymbolAddress((void**)&cursor, g_cursor);
    cudaGetSymbolAddress((void**)&csr, g_csr);
    cudaGetSymbolAddress((void**)&blksum, g_blksum);
    cudaGetSymbolAddress((void**)&blkoff, g_blkoff);

    cudaFuncSetAttribute(k_gemm3<64, 0>,  cudaFuncAttributeMaxDynamicSharedMemorySize, G3_SMEM);
    cudaFuncSetAttribute(k_gemm3<128, 0>, cudaFuncAttributeMaxDynamicSharedMemorySize, G3_SMEM);
    cudaFuncSetAttribute(k_gemm3<128, 1>, cudaFuncAttributeMaxDynamicSharedMemorySize, G3_SMEM);

    const int MB = (NN + 127) / 128;  // 391

    // (1) build B fragment images
    k_img<<<(IMG_TOTAL + 255) / 256, 256>>>(emb_W, Wl, Wr, p1_W, p2_W, img);
    // (2) bias packing
    k_bias<<<(LAYERS * 1024 + 255) / 256, 256>>>(bl, br, p2_b, bB, p2b);
    // (3) embedding: h = relu(x @ emb_W + emb_b)
    k_gemm3<64, 0><<<dim3(MB, 1), 128, G3_SMEM>>>(x, img + IMG_EMB, emb_b, hA, nullptr, NN, HID, 1);
    // (4) layer-1 split GEMM  <-- profiled slot
    k_gemm3<128, 1><<<dim3(MB, 8), 128, G3_SMEM>>>(hA, img + IMG_WB, bB, xr, xlh, NN, 1024, 0);
    // CSR build
    k_zero_int<<<(NN + 255) / 256, 256>>>(deg, NN);
    k_count_deg<<<(EE + 255) / 256, 256>>>(dstp, deg, EE);
    k_scan_part<<<NBLK, SCAN_B>>>(deg, offs, blksum, NN);
    k_scan_blk<<<1, 64>>>(blksum, blkoff, offs, NBLK, NN);
    k_scan_add<<<NBLK, SCAN_B>>>(offs, blkoff, cursor, NN);
    k_fill_csr<<<(EE + 255) / 256, 256>>>(srcp, dstp, cursor, csr, EE);

    // layer 1 edge
    float* hc = hA;
    float* hn = hB;
    k_gat_edge<<<(NN + 1) / 2, 256>>>(xlh, xr, att, cbias, hc, hn, offs, csr);
    { float* t = hc; hc = hn; hn = t; }

    // layers 2..3
    for (int l = 1; l < LAYERS; l++) {
        k_gemm3<128, 1><<<dim3(MB, 8), 128, G3_SMEM>>>(
            hc, img + IMG_WB + (size_t)l * 131072, bB + (size_t)l * 1024, xr, xlh, NN, 1024, 0);
        k_gat_edge<<<(NN + 1) / 2, 256>>>(xlh, xr, att + (size_t)l * HEADS * HID,
                                          cbias + l * HID, hc, hn, offs, csr);
        float* t = hc; hc = hn; hn = t;
    }

    // predictor MLP (z1/z2 carved out of xr scratch; z2 width 128, cols>=64 zero)
    float* z1 = xr;
    float* z2 = xr + (size_t)NN * HID;
    k_gemm3<128, 0><<<dim3(MB, 1), 128, G3_SMEM>>>(hc, img + IMG_P1, p1_b, z1, nullptr, NN, HID, 1);
    k_gemm3<128, 0><<<dim3(MB, 1), 128, G3_SMEM>>>(z1, img + IMG_P2, p2b, z2, nullptr, NN, 128, 1);
    k_pred3<<<(NN * 32 + 255) / 256, 256>>>(z2, p3_W, p3_b, out, NN);
}

// round 9
// speedup vs baseline: 1.4976x; 1.0579x over previous
#include <cuda_runtime.h>
#include <cuda_fp16.h>
#include <math.h>
#include <stdint.h>

#define NN   50000
#define EE   800000
#define FIN  64
#define HID  128
#define HEADS 4
#define HOUT 512
#define LAYERS 3
#define NEG_SLOPE 0.2f
#define SCAN_B 1024
#define NBLK ((NN + SCAN_B - 1) / SCAN_B)

// fp16 B fragment image: per n-block(128) per k-chunk(32): 2048 words (8KB)
#define IMG_EMB 0                        // nb=1, nc=2 -> 4096
#define IMG_WB  4096                     // 3 x (nb=8, nc=4) -> 65536 each
#define IMG_P1  (4096 + 3 * 65536)       // 8192
#define IMG_P2  (IMG_P1 + 8192)          // 8192
#define IMG_TOTAL (IMG_P2 + 8192)        // 217088

// ---------------- scratch ----------------
__device__ float    g_hA[(size_t)NN * HID];
__device__ float    g_hB[(size_t)NN * HID];
__device__ __half   g_hAh[(size_t)NN * HID];
__device__ __half   g_hBh[(size_t)NN * HID];
__device__ __half   g_xh[(size_t)NN * FIN];
__device__ __half   g_xlh[(size_t)NN * HOUT];   // fp16 xl (also reused as z1h)
__device__ float    g_xr[(size_t)NN * HOUT];    // fp32 xr / predictor scratch
__device__ uint32_t g_img[IMG_TOTAL];
__device__ float    g_bB[(size_t)LAYERS * 1024];
__device__ float    g_p2b[128];
__device__ int      g_deg[NN];
__device__ int      g_offs[NN + 1];
__device__ int      g_cursor[NN];
__device__ int      g_csr[EE];
__device__ int      g_blksum[NBLK];
__device__ int      g_blkoff[NBLK];

__device__ __forceinline__ void mma_f16(float* d, const uint32_t* a, const uint32_t* b) {
    asm volatile(
        "mma.sync.aligned.m16n8k16.row.col.f32.f16.f16.f32 "
        "{%0,%1,%2,%3}, {%4,%5,%6,%7}, {%8,%9}, {%0,%1,%2,%3};"
        : "+f"(d[0]), "+f"(d[1]), "+f"(d[2]), "+f"(d[3])
        : "r"(a[0]), "r"(a[1]), "r"(a[2]), "r"(a[3]), "r"(b[0]), "r"(b[1]));
}
__device__ __forceinline__ uint32_t smem_u32(const void* p) {
    uint32_t a;
    asm("{ .reg .u64 t; cvta.to.shared.u64 t, %1; cvt.u32.u64 %0, t; }" : "=r"(a) : "l"(p));
    return a;
}

// ---------------- prep: fp16 B fragment images + bias packing (one launch) ----------------
// image word u in chunk: u = (g*32 + lane)*4 + comp; comp = k16*2 + pairsel
//   halves: k = kc*32 + k16*16 + pairsel*8 + lig*2 (+1), n = blk*128 + g*8 + grp
__global__ void k_img(const float* __restrict__ emb_W, const float* __restrict__ Wl,
                      const float* __restrict__ Wr, const float* __restrict__ p1_W,
                      const float* __restrict__ p2_W,
                      const float* __restrict__ bl, const float* __restrict__ br,
                      const float* __restrict__ p2_b,
                      uint32_t* __restrict__ img, float* __restrict__ bB,
                      float* __restrict__ p2bp) {
    int w = blockIdx.x * blockDim.x + threadIdx.x;
    if (w >= IMG_TOTAL) return;
    if (w < LAYERS * 1024) {
        int l = w / 1024, n = w % 1024;
        bB[w] = (n < HOUT) ? bl[l * HOUT + n] : br[l * HOUT + n - HOUT];
    }
    if (w < 128) p2bp[w] = (w < 64) ? p2_b[w] : 0.f;

    int rem, nc, seg;
    if (w < IMG_WB)      { seg = 0; rem = w;           nc = 2; }
    else if (w < IMG_P1) { seg = 1; rem = w - IMG_WB;  nc = 4; }
    else if (w < IMG_P2) { seg = 2; rem = w - IMG_P1;  nc = 4; }
    else                 { seg = 3; rem = w - IMG_P2;  nc = 4; }
    int layer = 0;
    if (seg == 1) { layer = rem / 65536; rem %= 65536; }
    int cw = nc * 2048;
    int blk = rem / cw;
    int r2 = rem % cw;
    int kc = r2 / 2048;
    int u = r2 % 2048;
    int comp = u & 3;
    int lane = (u >> 2) & 31;
    int g = u >> 7;
    int lig = lane & 3, grp = lane >> 2;
    int k16 = comp >> 1, pairsel = comp & 1;
    int k = kc * 32 + k16 * 16 + pairsel * 8 + lig * 2;
    int n = blk * 128 + g * 8 + grp;
    float lo, hi;
    if (seg == 0) {
        lo = emb_W[k * HID + n];
        hi = emb_W[(k + 1) * HID + n];
    } else if (seg == 1) {
        if (n < HOUT) {
            lo = Wl[((size_t)layer * HID + k) * HOUT + n];
            hi = Wl[((size_t)layer * HID + k + 1) * HOUT + n];
        } else {
            lo = Wr[((size_t)layer * HID + k) * HOUT + (n - HOUT)];
            hi = Wr[((size_t)layer * HID + k + 1) * HOUT + (n - HOUT)];
        }
    } else if (seg == 2) {
        lo = p1_W[k * HID + n];
        hi = p1_W[(k + 1) * HID + n];
    } else {
        lo = (n < 64) ? p2_W[k * 64 + n] : 0.f;
        hi = (n < 64) ? p2_W[(k + 1) * 64 + n] : 0.f;
    }
    __half2 h2 = __floats2half2_rn(lo, hi);
    img[w] = *(uint32_t*)&h2;
}

// ---------------- x -> fp16 ----------------
__global__ void k_h2(const float* __restrict__ x, __half* __restrict__ xh, int n) {
    int i = blockIdx.x * blockDim.x + threadIdx.x;
    if (i < n) xh[i] = __float2half(x[i]);
}

// ---------------- CSR build ----------------
__global__ void k_zero_int(int* p, int n) {
    int i = blockIdx.x * blockDim.x + threadIdx.x;
    if (i < n) p[i] = 0;
}
__global__ void k_count_deg(const int* __restrict__ dst, int* __restrict__ deg, int e) {
    int i = blockIdx.x * blockDim.x + threadIdx.x;
    if (i < e) atomicAdd(&deg[dst[i]], 1);
}
__global__ void k_scan_part(const int* __restrict__ deg, int* __restrict__ offs,
                            int* __restrict__ blksum, int n) {
    __shared__ int wsum[32];
    int gid = blockIdx.x * SCAN_B + threadIdx.x;
    int lane = threadIdx.x & 31, wid = threadIdx.x >> 5;
    int v = (gid < n) ? deg[gid] : 0;
    int s = v;
    #pragma unroll
    for (int o = 1; o < 32; o <<= 1) {
        int t = __shfl_up_sync(0xffffffffu, s, o);
        if (lane >= o) s += t;
    }
    if (lane == 31) wsum[wid] = s;
    __syncthreads();
    if (wid == 0) {
        int ws = wsum[lane];
        #pragma unroll
        for (int o = 1; o < 32; o <<= 1) {
            int t = __shfl_up_sync(0xffffffffu, ws, o);
            if (lane >= o) ws += t;
        }
        wsum[lane] = ws;
    }
    __syncthreads();
    int base = wid ? wsum[wid - 1] : 0;
    int incl = base + s;
    if (gid < n) offs[gid] = incl - v;
    if (threadIdx.x == SCAN_B - 1) blksum[blockIdx.x] = incl;
}
__global__ void k_scan_blk(const int* __restrict__ blksum, int* __restrict__ blkoff,
                           int* __restrict__ offs, int nblk, int n) {
    __shared__ int sm[64];
    int t = threadIdx.x;
    int v = (t < nblk) ? blksum[t] : 0;
    sm[t] = v;
    __syncthreads();
    #pragma unroll
    for (int d = 1; d < 64; d <<= 1) {
        int tv = (t >= d) ? sm[t - d] : 0;
        __syncthreads();
        sm[t] += tv;
        __syncthreads();
    }
    if (t < nblk) blkoff[t] = sm[t] - v;
    if (t == 63) offs[n] = sm[63];
}
__global__ void k_scan_add(int* __restrict__ offs, const int* __restrict__ blkoff,
                           int* __restrict__ cursor, int n) {
    int gid = blockIdx.x * SCAN_B + threadIdx.x;
    if (gid < n) {
        int o = offs[gid] + blkoff[blockIdx.x];
        offs[gid] = o;
        cursor[gid] = o;
    }
}
__global__ void k_fill_csr(const int* __restrict__ src, const int* __restrict__ dst,
                           int* __restrict__ cursor, int* __restrict__ csr, int e) {
    int i = blockIdx.x * blockDim.x + threadIdx.x;
    if (i < e) {
        int p = atomicAdd(&cursor[dst[i]], 1);
        csr[p] = src[i];
    }
}

// ---------------- GEMM v4: fp16 mma, 4 warps of 64x64, cp.async, B fragment image ----------------
// A fp16 smem rows stride 20 words (conflict-free fragment loads). Buffer = 2560(A)+2048(B) words.
#define ABUF_W 2560
#define BUF_W  4608
#define G4_SMEM (2 * BUF_W * 4)   // 36864

template <int KT, int MODE>
__global__ __launch_bounds__(128, 2) void k_gemm4(
    const __half* __restrict__ A, const uint32_t* __restrict__ img,
    const float* __restrict__ bias, float* __restrict__ C, __half* __restrict__ Ch,
    int M, int Ns, int relu) {
    extern __shared__ uint32_t sm[];
    constexpr int NK = KT / 32;
    int tid = threadIdx.x;
    int wid = tid >> 5, lane = tid & 31;
    int grp = lane >> 2, lig = lane & 3;
    const int wm = (wid & 1) * 64;
    const int wg8 = (wid >> 1) * 8;
    const int bm = blockIdx.x * 128, bn = blockIdx.y * 128;
    const uint32_t* imgB = img + (size_t)blockIdx.y * NK * 2048;
    uint32_t sbase = smem_u32(sm);

    float acc[4][8][4];
    #pragma unroll
    for (int i = 0; i < 4; i++)
        #pragma unroll
        for (int j = 0; j < 8; j++)
            #pragma unroll
            for (int q = 0; q < 4; q++) acc[i][j][q] = 0.f;

    auto stage = [&](int kc, int b) {
        uint32_t abase = sbase + b * (BUF_W * 4);
        // A: 128 rows x 32 halves; 8B copies, 8 per thread
        #pragma unroll
        for (int i = 0; i < 8; i++) {
            int idx = tid + i * 128;
            int r = idx >> 3, s = idx & 7;
            int gr = bm + r;
            uint32_t dst = abase + (uint32_t)(r * 80 + s * 8);
            const __half* src = A + (size_t)gr * KT + kc * 32 + s * 4;
            int sz = (gr < M) ? 8 : 0;
            asm volatile("cp.async.ca.shared.global [%0], [%1], 8, %2;"
                         :: "r"(dst), "l"(src), "r"(sz));
        }
        // B: 2048 words; 16B copies, 4 per thread
        uint32_t bbase = abase + ABUF_W * 4;
        const uint32_t* bsrc = imgB + kc * 2048;
        #pragma unroll
        for (int i = 0; i < 4; i++) {
            int idx = tid + i * 128;
            uint32_t dst = bbase + (uint32_t)idx * 16;
            asm volatile("cp.async.ca.shared.global [%0], [%1], 16, 16;"
                         :: "r"(dst), "l"(bsrc + idx * 4));
        }
        asm volatile("cp.async.commit_group;");
    };

    stage(0, 0);
    int buf = 0;
    #pragma unroll
    for (int kc = 0; kc < NK; kc++) {
        asm volatile("cp.async.wait_group 0;");
        __syncthreads();
        if (kc + 1 < NK) stage(kc + 1, buf ^ 1);

        const uint32_t* As = sm + buf * BUF_W;
        const uint32_t* Bs = As + ABUF_W;
        uint4 bq[8];
        #pragma unroll
        for (int nt = 0; nt < 8; nt++)
            bq[nt] = *(const uint4*)(Bs + ((wg8 + nt) * 32 + lane) * 4);
        #pragma unroll
        for (int k16 = 0; k16 < 2; k16++) {
            #pragma unroll
            for (int mt = 0; mt < 4; mt++) {
                int rw = (wm + mt * 16 + grp) * 20 + k16 * 8 + lig;
                uint32_t av[4];
                av[0] = As[rw];
                av[1] = As[rw + 160];
                av[2] = As[rw + 4];
                av[3] = As[rw + 164];
                #pragma unroll
                for (int nt = 0; nt < 8; nt++) {
                    uint32_t bv[2];
                    if (k16 == 0) { bv[0] = bq[nt].x; bv[1] = bq[nt].y; }
                    else          { bv[0] = bq[nt].z; bv[1] = bq[nt].w; }
                    mma_f16(acc[mt][nt], av, bv);
                }
            }
        }
        buf ^= 1;
    }

    // epilogue
    #pragma unroll
    for (int mt = 0; mt < 4; mt++) {
        #pragma unroll
        for (int nt = 0; nt < 8; nt++) {
            int col = bn + (wg8 + nt) * 8 + lig * 2;
            float b0 = __ldg(bias + col), b1 = __ldg(bias + col + 1);
            int row0 = bm + wm + mt * 16 + grp;
            int row1 = row0 + 8;
            float v0 = acc[mt][nt][0] + b0;
            float v1 = acc[mt][nt][1] + b1;
            float v2 = acc[mt][nt][2] + b0;
            float v3 = acc[mt][nt][3] + b1;
            if (relu) {
                v0 = fmaxf(v0, 0.f); v1 = fmaxf(v1, 0.f);
                v2 = fmaxf(v2, 0.f); v3 = fmaxf(v3, 0.f);
            }
            if (MODE == 0) {
                if (row0 < M) {
                    *(float2*)(C + (size_t)row0 * Ns + col) = make_float2(v0, v1);
                    if (Ch) *(__half2*)(Ch + (size_t)row0 * Ns + col) = __floats2half2_rn(v0, v1);
                }
                if (row1 < M) {
                    *(float2*)(C + (size_t)row1 * Ns + col) = make_float2(v2, v3);
                    if (Ch) *(__half2*)(Ch + (size_t)row1 * Ns + col) = __floats2half2_rn(v2, v3);
                }
            } else {
                if (col < HOUT) {
                    if (row0 < M) *(__half2*)(Ch + (size_t)row0 * HOUT + col) = __floats2half2_rn(v0, v1);
                    if (row1 < M) *(__half2*)(Ch + (size_t)row1 * HOUT + col) = __floats2half2_rn(v2, v3);
                } else {
                    int c2 = col - HOUT;
                    if (row0 < M) *(float2*)(C + (size_t)row0 * HOUT + c2) = make_float2(v0, v1);
                    if (row1 < M) *(float2*)(C + (size_t)row1 * HOUT + c2) = make_float2(v2, v3);
                }
            }
        }
    }
}

// ---------------- GATv2 edge kernel: fp16 xl, 4-way unrolled online softmax ----------------
__device__ __forceinline__ float4 ld_xl(const __half* __restrict__ xlh, int s, int off) {
    uint2 raw = *(const uint2*)(xlh + (size_t)s * HOUT + off);
    float2 f01 = __half22float2(*(__half2*)&raw.x);
    float2 f23 = __half22float2(*(__half2*)&raw.y);
    return make_float4(f01.x, f01.y, f23.x, f23.y);
}
__device__ __forceinline__ float leaky_dot(const float4 av, const float4 v, const float4 xrv) {
    float m0 = v.x + xrv.x; m0 = m0 > 0.f ? m0 : NEG_SLOPE * m0;
    float m1 = v.y + xrv.y; m1 = m1 > 0.f ? m1 : NEG_SLOPE * m1;
    float m2 = v.z + xrv.z; m2 = m2 > 0.f ? m2 : NEG_SLOPE * m2;
    float m3 = v.w + xrv.w; m3 = m3 > 0.f ? m3 : NEG_SLOPE * m3;
    return av.x * m0 + av.y * m1 + av.z * m2 + av.w * m3;
}

__global__ __launch_bounds__(256) void k_gat_edge(
    const __half* __restrict__ xlh, const float* __restrict__ xr,
    const float* __restrict__ att, const float* __restrict__ cbias,
    const float* __restrict__ hin, float* __restrict__ hout, __half* __restrict__ houth,
    const int* __restrict__ offs, const int* __restrict__ csr) {
    int half_ = threadIdx.x >> 7;
    int node = blockIdx.x * 2 + half_;
    int t128 = threadIdx.x & 127;
    int w = t128 >> 5, lane = threadIdx.x & 31;
    __shared__ float hacc[2][HEADS][HID];

    if (node < NN) {
        int beg = offs[node], end = offs[node + 1];
        const int off = w * HID + lane * 4;
        const float4 xrv = *(const float4*)(xr + (size_t)node * HOUT + off);
        const float4 av  = *(const float4*)(att + w * HID + lane * 4);

        float emax = -1e30f, denom = 0.f;
        float4 acc = make_float4(0.f, 0.f, 0.f, 0.f);
        int i = beg;
        for (; i + 3 < end; i += 4) {
            int s0 = __ldg(csr + i),     s1 = __ldg(csr + i + 1);
            int s2 = __ldg(csr + i + 2), s3 = __ldg(csr + i + 3);
            float4 v0 = ld_xl(xlh, s0, off);
            float4 v1 = ld_xl(xlh, s1, off);
            float4 v2 = ld_xl(xlh, s2, off);
            float4 v3 = ld_xl(xlh, s3, off);
            float p0 = leaky_dot(av, v0, xrv);
            float p1 = leaky_dot(av, v1, xrv);
            float p2 = leaky_dot(av, v2, xrv);
            float p3 = leaky_dot(av, v3, xrv);
            #pragma unroll
            for (int o = 16; o; o >>= 1) {
                p0 += __shfl_xor_sync(0xffffffffu, p0, o);
                p1 += __shfl_xor_sync(0xffffffffu, p1, o);
                p2 += __shfl_xor_sync(0xffffffffu, p2, o);
                p3 += __shfl_xor_sync(0xffffffffu, p3, o);
            }
            float nm = fmaxf(fmaxf(emax, fmaxf(p0, p1)), fmaxf(p2, p3));
            float sc = __expf(emax - nm);
            denom *= sc;
            acc.x *= sc; acc.y *= sc; acc.z *= sc; acc.w *= sc;
            emax = nm;
            float w0 = __expf(p0 - nm), w1 = __expf(p1 - nm);
            float w2 = __expf(p2 - nm), w3 = __expf(p3 - nm);
            denom += (w0 + w1) + (w2 + w3);
            acc.x += w0 * v0.x + w1 * v1.x + w2 * v2.x + w3 * v3.x;
            acc.y += w0 * v0.y + w1 * v1.y + w2 * v2.y + w3 * v3.y;
            acc.z += w0 * v0.z + w1 * v1.z + w2 * v2.z + w3 * v3.z;
            acc.w += w0 * v0.w + w1 * v1.w + w2 * v2.w + w3 * v3.w;
        }
        for (; i < end; i++) {
            int s0 = __ldg(csr + i);
            float4 v0 = ld_xl(xlh, s0, off);
            float p0 = leaky_dot(av, v0, xrv);
            #pragma unroll
            for (int o = 16; o; o >>= 1) p0 += __shfl_xor_sync(0xffffffffu, p0, o);
            float nm = fmaxf(emax, p0);
            float sc = __expf(emax - nm);
            denom *= sc;
            acc.x *= sc; acc.y *= sc; acc.z *= sc; acc.w *= sc;
            emax = nm;
            float w0 = __expf(p0 - nm);
            denom += w0;
            acc.x += w0 * v0.x; acc.y += w0 * v0.y;
            acc.z += w0 * v0.z; acc.w += w0 * v0.w;
        }
        float inv = denom > 0.f ? 1.f / denom : 0.f;
        hacc[half_][w][lane * 4 + 0] = acc.x * inv;
        hacc[half_][w][lane * 4 + 1] = acc.y * inv;
        hacc[half_][w][lane * 4 + 2] = acc.z * inv;
        hacc[half_][w][lane * 4 + 3] = acc.w * inv;
    }
    __syncthreads();
    if (node < NN) {
        float sv = (hacc[half_][0][t128] + hacc[half_][1][t128] +
                    hacc[half_][2][t128] + hacc[half_][3][t128]) * 0.25f
                 + cbias[t128] + hin[(size_t)node * HID + t128];
        sv = fmaxf(sv, 0.f);
        hout[(size_t)node * HID + t128] = sv;
        houth[(size_t)node * HID + t128] = __float2half(sv);
    }
}

// ---------------- final predictor head (z2 fp32, row stride 128) ----------------
__global__ void k_pred3(const float* __restrict__ z2, const float* __restrict__ W,
                        const float* __restrict__ b, float* __restrict__ out, int n) {
    int warp = (blockIdx.x * blockDim.x + threadIdx.x) >> 5;
    int lane = threadIdx.x & 31;
    if (warp >= n) return;
    const float* zr = z2 + (size_t)warp * 128;
    float p = zr[lane] * W[lane] + zr[lane + 32] * W[lane + 32];
    #pragma unroll
    for (int o = 16; o; o >>= 1) p += __shfl_xor_sync(0xffffffffu, p, o);
    if (lane == 0) {
        float s = p + b[0];
        s = fminf(fmaxf(s, -15.f), 15.f);
        out[warp] = s;
    }
}

// ---------------- launch ----------------
extern "C" void kernel_launch(void* const* d_in, const int* in_sizes, int n_in,
                              void* d_out, int out_size) {
    const float* x      = (const float*)d_in[0];
    const int*   eidx   = (const int*)d_in[1];
    const float* emb_W  = (const float*)d_in[3];
    const float* emb_b  = (const float*)d_in[4];
    const float* Wl     = (const float*)d_in[5];
    const float* bl     = (const float*)d_in[6];
    const float* Wr     = (const float*)d_in[7];
    const float* br     = (const float*)d_in[8];
    const float* att    = (const float*)d_in[9];
    const float* cbias  = (const float*)d_in[10];
    const float* p1_W   = (const float*)d_in[11];
    const float* p1_b   = (const float*)d_in[12];
    const float* p2_W   = (const float*)d_in[13];
    const float* p2_b   = (const float*)d_in[14];
    const float* p3_W   = (const float*)d_in[15];
    const float* p3_b   = (const float*)d_in[16];
    float* out = (float*)d_out;

    const int* srcp = eidx;
    const int* dstp = eidx + EE;

    float *hA, *hB, *xr, *bB, *p2b;
    __half *hAh, *hBh, *xh, *xlh;
    uint32_t* img;
    int *deg, *offs, *cursor, *csr, *blksum, *blkoff;
    cudaGetSymbolAddress((void**)&hA, g_hA);
    cudaGetSymbolAddress((void**)&hB, g_hB);
    cudaGetSymbolAddress((void**)&hAh, g_hAh);
    cudaGetSymbolAddress((void**)&hBh, g_hBh);
    cudaGetSymbolAddress((void**)&xh, g_xh);
    cudaGetSymbolAddress((void**)&xlh, g_xlh);
    cudaGetSymbolAddress((void**)&xr, g_xr);
    cudaGetSymbolAddress((void**)&img, g_img);
    cudaGetSymbolAddress((void**)&bB, g_bB);
    cudaGetSymbolAddress((void**)&p2b, g_p2b);
    cudaGetSymbolAddress((void**)&deg, g_deg);
    cudaGetSymbolAddress((void**)&offs, g_offs);
    cudaGetSymbolAddress((void**)&cursor, g_cursor);
    cudaGetSymbolAddress((void**)&csr, g_csr);
    cudaGetSymbolAddress((void**)&blksum, g_blksum);
    cudaGetSymbolAddress((void**)&blkoff, g_blkoff);

    cudaFuncSetAttribute(k_gemm4<64, 0>,  cudaFuncAttributeMaxDynamicSharedMemorySize, G4_SMEM);
    cudaFuncSetAttribute(k_gemm4<128, 0>, cudaFuncAttributeMaxDynamicSharedMemorySize, G4_SMEM);
    cudaFuncSetAttribute(k_gemm4<128, 1>, cudaFuncAttributeMaxDynamicSharedMemorySize, G4_SMEM);

    const int MB = (NN + 127) / 128;  // 391

    // (1) fp16 fragment images + bias packing
    k_img<<<(IMG_TOTAL + 255) / 256, 256>>>(emb_W, Wl, Wr, p1_W, p2_W, bl, br, p2_b,
                                            img, bB, p2b);
    // (2) x -> fp16
    k_h2<<<(NN * FIN + 255) / 256, 256>>>(x, xh, NN * FIN);
    // (3) embedding: h = relu(x @ emb_W + emb_b), fp32 + fp16 out
    k_gemm4<64, 0><<<dim3(MB, 1), 128, G4_SMEM>>>(xh, img + IMG_EMB, emb_b, hA, hAh, NN, HID, 1);
    // (4) layer-1 split GEMM  <-- profiled slot
    k_gemm4<128, 1><<<dim3(MB, 8), 128, G4_SMEM>>>(hAh, img + IMG_WB, bB, xr, xlh, NN, 1024, 0);
    // CSR build
    k_zero_int<<<(NN + 255) / 256, 256>>>(deg, NN);
    k_count_deg<<<(EE + 255) / 256, 256>>>(dstp, deg, EE);
    k_scan_part<<<NBLK, SCAN_B>>>(deg, offs, blksum, NN);
    k_scan_blk<<<1, 64>>>(blksum, blkoff, offs, NBLK, NN);
    k_scan_add<<<NBLK, SCAN_B>>>(offs, blkoff, cursor, NN);
    k_fill_csr<<<(EE + 255) / 256, 256>>>(srcp, dstp, cursor, csr, EE);

    // layer 1 edge
    float* hc = hA;   __half* hch = hAh;
    float* hn = hB;   __half* hnh = hBh;
    k_gat_edge<<<(NN + 1) / 2, 256>>>(xlh, xr, att, cbias, hc, hn, hnh, offs, csr);
    { float* t = hc; hc = hn; hn = t; __half* th = hch; hch = hnh; hnh = th; }

    // layers 2..3
    for (int l = 1; l < LAYERS; l++) {
        k_gemm4<128, 1><<<dim3(MB, 8), 128, G4_SMEM>>>(
            hch, img + IMG_WB + (size_t)l * 65536, bB + (size_t)l * 1024, xr, xlh, NN, 1024, 0);
        k_gat_edge<<<(NN + 1) / 2, 256>>>(xlh, xr, att + (size_t)l * HEADS * HID,
                                          cbias + l * HID, hc, hn, hnh, offs, csr);
        float* t = hc; hc = hn; hn = t; __half* th = hch; hch = hnh; hnh = th;
    }

    // predictor MLP: z1 fp32+fp16 (z1h reuses xlh), z2 fp32
    float* z1f = xr;
    __half* z1h = xlh;
    float* z2 = xr + (size_t)NN * HID;
    k_gemm4<128, 0><<<dim3(MB, 1), 128, G4_SMEM>>>(hch, img + IMG_P1, p1_b, z1f, z1h, NN, HID, 1);
    k_gemm4<128, 0><<<dim3(MB, 1), 128, G4_SMEM>>>(z1h, img + IMG_P2, p2b, z2, nullptr, NN, HID, 1);
    k_pred3<<<(NN * 32 + 255) / 256, 256>>>(z2, p3_W, p3_b, out, NN);
}

// round 10
// speedup vs baseline: 1.6085x; 1.0741x over previous
#include <cuda_runtime.h>
#include <cuda_fp16.h>
#include <math.h>
#include <stdint.h>

#define NN   50000
#define EE   800000
#define FIN  64
#define HID  128
#define HEADS 4
#define HOUT 512
#define LAYERS 3
#define NEG_SLOPE 0.2f
#define SCAN_B 1024
#define NBLK ((NN + SCAN_B - 1) / SCAN_B)

// fp16 B fragment image: per n-block(128) per k-chunk(32): 2048 words (8KB)
#define IMG_EMB 0                        // nb=1, nc=2 -> 4096
#define IMG_WB  4096                     // 3 x (nb=8, nc=4) -> 65536 each
#define IMG_P1  (4096 + 3 * 65536)
#define IMG_P2  (IMG_P1 + 8192)
#define IMG_TOTAL (IMG_P2 + 8192)

// ---------------- scratch ----------------
__device__ float    g_hA[(size_t)NN * HID];
__device__ float    g_hB[(size_t)NN * HID];
__device__ __half   g_hAh[(size_t)NN * HID];
__device__ __half   g_hBh[(size_t)NN * HID];
__device__ __half   g_xh[(size_t)NN * FIN];
__device__ __half   g_xlrh[(size_t)NN * 1024];  // fp16 [xl(512)|xr(512)]; reused as z1h
__device__ float    g_zf[(size_t)NN * 256];     // predictor fp32 scratch (z1,z2)
__device__ uint32_t g_img[IMG_TOTAL];
__device__ float    g_bB[(size_t)LAYERS * 1024];
__device__ float    g_p2b[128];
__device__ int      g_deg[NN];
__device__ int      g_offs[NN + 1];
__device__ int      g_cursor[NN];
__device__ int      g_csr[EE];
__device__ int      g_blksum[NBLK];
__device__ int      g_blkoff[NBLK];

__device__ __forceinline__ void mma_f16(float* d, const uint32_t* a, const uint32_t* b) {
    asm volatile(
        "mma.sync.aligned.m16n8k16.row.col.f32.f16.f16.f32 "
        "{%0,%1,%2,%3}, {%4,%5,%6,%7}, {%8,%9}, {%0,%1,%2,%3};"
        : "+f"(d[0]), "+f"(d[1]), "+f"(d[2]), "+f"(d[3])
        : "r"(a[0]), "r"(a[1]), "r"(a[2]), "r"(a[3]), "r"(b[0]), "r"(b[1]));
}
__device__ __forceinline__ uint32_t smem_u32(const void* p) {
    uint32_t a;
    asm("{ .reg .u64 t; cvta.to.shared.u64 t, %1; cvt.u32.u64 %0, t; }" : "=r"(a) : "l"(p));
    return a;
}

// ---------------- prep: fp16 B fragment images + bias packing ----------------
__global__ void k_img(const float* __restrict__ emb_W, const float* __restrict__ Wl,
                      const float* __restrict__ Wr, const float* __restrict__ p1_W,
                      const float* __restrict__ p2_W,
                      const float* __restrict__ bl, const float* __restrict__ br,
                      const float* __restrict__ p2_b,
                      uint32_t* __restrict__ img, float* __restrict__ bB,
                      float* __restrict__ p2bp) {
    int w = blockIdx.x * blockDim.x + threadIdx.x;
    if (w >= IMG_TOTAL) return;
    if (w < LAYERS * 1024) {
        int l = w / 1024, n = w % 1024;
        bB[w] = (n < HOUT) ? bl[l * HOUT + n] : br[l * HOUT + n - HOUT];
    }
    if (w < 128) p2bp[w] = (w < 64) ? p2_b[w] : 0.f;

    int rem, nc, seg;
    if (w < IMG_WB)      { seg = 0; rem = w;           nc = 2; }
    else if (w < IMG_P1) { seg = 1; rem = w - IMG_WB;  nc = 4; }
    else if (w < IMG_P2) { seg = 2; rem = w - IMG_P1;  nc = 4; }
    else                 { seg = 3; rem = w - IMG_P2;  nc = 4; }
    int layer = 0;
    if (seg == 1) { layer = rem / 65536; rem %= 65536; }
    int cw = nc * 2048;
    int blk = rem / cw;
    int r2 = rem % cw;
    int kc = r2 / 2048;
    int u = r2 % 2048;
    int comp = u & 3;
    int lane = (u >> 2) & 31;
    int g = u >> 7;
    int lig = lane & 3, grp = lane >> 2;
    int k16 = comp >> 1, pairsel = comp & 1;
    int k = kc * 32 + k16 * 16 + pairsel * 8 + lig * 2;
    int n = blk * 128 + g * 8 + grp;
    float lo, hi;
    if (seg == 0) {
        lo = emb_W[k * HID + n];
        hi = emb_W[(k + 1) * HID + n];
    } else if (seg == 1) {
        if (n < HOUT) {
            lo = Wl[((size_t)layer * HID + k) * HOUT + n];
            hi = Wl[((size_t)layer * HID + k + 1) * HOUT + n];
        } else {
            lo = Wr[((size_t)layer * HID + k) * HOUT + (n - HOUT)];
            hi = Wr[((size_t)layer * HID + k + 1) * HOUT + (n - HOUT)];
        }
    } else if (seg == 2) {
        lo = p1_W[k * HID + n];
        hi = p1_W[(k + 1) * HID + n];
    } else {
        lo = (n < 64) ? p2_W[k * 64 + n] : 0.f;
        hi = (n < 64) ? p2_W[(k + 1) * 64 + n] : 0.f;
    }
    __half2 h2 = __floats2half2_rn(lo, hi);
    img[w] = *(uint32_t*)&h2;
}

__global__ void k_h2(const float* __restrict__ x, __half* __restrict__ xh, int n) {
    int i = blockIdx.x * blockDim.x + threadIdx.x;
    if (i < n) xh[i] = __float2half(x[i]);
}

// ---------------- CSR build ----------------
__global__ void k_zero_int(int* p, int n) {
    int i = blockIdx.x * blockDim.x + threadIdx.x;
    if (i < n) p[i] = 0;
}
__global__ void k_count_deg(const int* __restrict__ dst, int* __restrict__ deg, int e) {
    int i = blockIdx.x * blockDim.x + threadIdx.x;
    if (i < e) atomicAdd(&deg[dst[i]], 1);
}
__global__ void k_scan_part(const int* __restrict__ deg, int* __restrict__ offs,
                            int* __restrict__ blksum, int n) {
    __shared__ int wsum[32];
    int gid = blockIdx.x * SCAN_B + threadIdx.x;
    int lane = threadIdx.x & 31, wid = threadIdx.x >> 5;
    int v = (gid < n) ? deg[gid] : 0;
    int s = v;
    #pragma unroll
    for (int o = 1; o < 32; o <<= 1) {
        int t = __shfl_up_sync(0xffffffffu, s, o);
        if (lane >= o) s += t;
    }
    if (lane == 31) wsum[wid] = s;
    __syncthreads();
    if (wid == 0) {
        int ws = wsum[lane];
        #pragma unroll
        for (int o = 1; o < 32; o <<= 1) {
            int t = __shfl_up_sync(0xffffffffu, ws, o);
            if (lane >= o) ws += t;
        }
        wsum[lane] = ws;
    }
    __syncthreads();
    int base = wid ? wsum[wid - 1] : 0;
    int incl = base + s;
    if (gid < n) offs[gid] = incl - v;
    if (threadIdx.x == SCAN_B - 1) blksum[blockIdx.x] = incl;
}
__global__ void k_scan_blk(const int* __restrict__ blksum, int* __restrict__ blkoff,
                           int* __restrict__ offs, int nblk, int n) {
    __shared__ int sm[64];
    int t = threadIdx.x;
    int v = (t < nblk) ? blksum[t] : 0;
    sm[t] = v;
    __syncthreads();
    #pragma unroll
    for (int d = 1; d < 64; d <<= 1) {
        int tv = (t >= d) ? sm[t - d] : 0;
        __syncthreads();
        sm[t] += tv;
        __syncthreads();
    }
    if (t < nblk) blkoff[t] = sm[t] - v;
    if (t == 63) offs[n] = sm[63];
}
__global__ void k_scan_add(int* __restrict__ offs, const int* __restrict__ blkoff,
                           int* __restrict__ cursor, int n) {
    int gid = blockIdx.x * SCAN_B + threadIdx.x;
    if (gid < n) {
        int o = offs[gid] + blkoff[blockIdx.x];
        offs[gid] = o;
        cursor[gid] = o;
    }
}
__global__ void k_fill_csr(const int* __restrict__ src, const int* __restrict__ dst,
                           int* __restrict__ cursor, int* __restrict__ csr, int e) {
    int i = blockIdx.x * blockDim.x + threadIdx.x;
    if (i < e) {
        int p = atomicAdd(&cursor[dst[i]], 1);
        csr[p] = src[i];
    }
}

// ---------------- GEMM v5: fp16 mma, full-K cp.async pipeline (up to 4 stages) ----------------
#define STAGE_B 18432                 // bytes per stage: A 2560w + B 2048w
#define G5_SMEM (4 * STAGE_B)         // 73728

#define CPWAIT(n) asm volatile("cp.async.wait_group " #n ";")

template <int KT, int MODE>
__global__ __launch_bounds__(128, 2) void k_gemm5(
    const __half* __restrict__ A, const uint32_t* __restrict__ img,
    const float* __restrict__ bias, float* __restrict__ C, __half* __restrict__ Ch,
    int M, int Ns, int relu) {
    extern __shared__ uint32_t sm[];
    constexpr int NK = KT / 32;
    int tid = threadIdx.x;
    int wid = tid >> 5, lane = tid & 31;
    int grp = lane >> 2, lig = lane & 3;
    const int wm = (wid & 1) * 64;
    const int wg8 = (wid >> 1) * 8;
    const int bm = blockIdx.x * 128, bn = blockIdx.y * 128;
    const uint32_t* imgB = img + (size_t)blockIdx.y * NK * 2048;
    uint32_t sbase = smem_u32(sm);

    float acc[4][8][4];
    #pragma unroll
    for (int i = 0; i < 4; i++)
        #pragma unroll
        for (int j = 0; j < 8; j++)
            #pragma unroll
            for (int q = 0; q < 4; q++) acc[i][j][q] = 0.f;

    auto stage = [&](int kc) {
        uint32_t abase = sbase + kc * STAGE_B;
        #pragma unroll
        for (int i = 0; i < 8; i++) {
            int idx = tid + i * 128;
            int r = idx >> 3, s = idx & 7;
            int gr = bm + r;
            uint32_t dst = abase + (uint32_t)(r * 80 + s * 8);
            const __half* src = A + (size_t)gr * KT + kc * 32 + s * 4;
            int sz = (gr < M) ? 8 : 0;
            asm volatile("cp.async.ca.shared.global [%0], [%1], 8, %2;"
                         :: "r"(dst), "l"(src), "r"(sz));
        }
        uint32_t bbase = abase + 2560 * 4;
        const uint32_t* bsrc = imgB + kc * 2048;
        #pragma unroll
        for (int i = 0; i < 4; i++) {
            int idx = tid + i * 128;
            uint32_t dst = bbase + (uint32_t)idx * 16;
            asm volatile("cp.async.ca.shared.global [%0], [%1], 16, 16;"
                         :: "r"(dst), "l"(bsrc + idx * 4));
        }
        asm volatile("cp.async.commit_group;");
    };

    #pragma unroll
    for (int kc = 0; kc < NK; kc++) stage(kc);

    auto compute = [&](int kc) {
        const uint32_t* As = sm + kc * 4608;
        const uint32_t* Bs = As + 2560;
        uint4 bq[8];
        #pragma unroll
        for (int nt = 0; nt < 8; nt++)
            bq[nt] = *(const uint4*)(Bs + ((wg8 + nt) * 32 + lane) * 4);
        #pragma unroll
        for (int k16 = 0; k16 < 2; k16++) {
            #pragma unroll
            for (int mt = 0; mt < 4; mt++) {
                int rw = (wm + mt * 16 + grp) * 20 + k16 * 8 + lig;
                uint32_t av[4];
                av[0] = As[rw];
                av[1] = As[rw + 160];
                av[2] = As[rw + 4];
                av[3] = As[rw + 164];
                #pragma unroll
                for (int nt = 0; nt < 8; nt++) {
                    uint32_t bv[2];
                    if (k16 == 0) { bv[0] = bq[nt].x; bv[1] = bq[nt].y; }
                    else          { bv[0] = bq[nt].z; bv[1] = bq[nt].w; }
                    mma_f16(acc[mt][nt], av, bv);
                }
            }
        }
    };

    if (NK == 4) {
        CPWAIT(3); __syncthreads(); compute(0);
        CPWAIT(2); __syncthreads(); compute(1);
        CPWAIT(1); __syncthreads(); compute(2);
        CPWAIT(0); __syncthreads(); compute(3);
    } else {
        CPWAIT(1); __syncthreads(); compute(0);
        CPWAIT(0); __syncthreads(); compute(1);
    }

    // epilogue
    #pragma unroll
    for (int mt = 0; mt < 4; mt++) {
        #pragma unroll
        for (int nt = 0; nt < 8; nt++) {
            int col = bn + (wg8 + nt) * 8 + lig * 2;
            float b0 = __ldg(bias + col), b1 = __ldg(bias + col + 1);
            int row0 = bm + wm + mt * 16 + grp;
            int row1 = row0 + 8;
            float v0 = acc[mt][nt][0] + b0;
            float v1 = acc[mt][nt][1] + b1;
            float v2 = acc[mt][nt][2] + b0;
            float v3 = acc[mt][nt][3] + b1;
            if (relu) {
                v0 = fmaxf(v0, 0.f); v1 = fmaxf(v1, 0.f);
                v2 = fmaxf(v2, 0.f); v3 = fmaxf(v3, 0.f);
            }
            if (MODE == 0) {
                if (row0 < M) {
                    *(float2*)(C + (size_t)row0 * Ns + col) = make_float2(v0, v1);
                    if (Ch) *(__half2*)(Ch + (size_t)row0 * Ns + col) = __floats2half2_rn(v0, v1);
                }
                if (row1 < M) {
                    *(float2*)(C + (size_t)row1 * Ns + col) = make_float2(v2, v3);
                    if (Ch) *(__half2*)(Ch + (size_t)row1 * Ns + col) = __floats2half2_rn(v2, v3);
                }
            } else {  // all cols -> fp16, stride 1024 ([xl|xr] merged)
                if (row0 < M) *(__half2*)(Ch + (size_t)row0 * 1024 + col) = __floats2half2_rn(v0, v1);
                if (row1 < M) *(__half2*)(Ch + (size_t)row1 * 1024 + col) = __floats2half2_rn(v2, v3);
            }
        }
    }
}

// ---------------- GATv2 edge kernel: fp16 xl|xr, half2 dot, 4-way unroll ----------------
__device__ __forceinline__ float h2dot(const __half2 a01, const __half2 a23,
                                       const __half2 xr01, const __half2 xr23,
                                       const __half2 neg2,
                                       const uint2 raw, float2* f01, float2* f23) {
    __half2 v01 = *(const __half2*)&raw.x, v23 = *(const __half2*)&raw.y;
    __half2 m01 = __hadd2(v01, xr01), m23 = __hadd2(v23, xr23);
    m01 = __hmax2(m01, __hmul2(m01, neg2));
    m23 = __hmax2(m23, __hmul2(m23, neg2));
    __half2 d2 = __hfma2(a23, m23, __hmul2(a01, m01));
    float2 df = __half22float2(d2);
    *f01 = __half22float2(v01);
    *f23 = __half22float2(v23);
    return df.x + df.y;
}

__global__ __launch_bounds__(256) void k_gat_edge(
    const __half* __restrict__ xlr, const float* __restrict__ att,
    const float* __restrict__ cbias,
    const float* __restrict__ hin, float* __restrict__ hout, __half* __restrict__ houth,
    const int* __restrict__ offs, const int* __restrict__ csr) {
    int half_ = threadIdx.x >> 7;
    int node = blockIdx.x * 2 + half_;
    int t128 = threadIdx.x & 127;
    int w = t128 >> 5, lane = threadIdx.x & 31;
    __shared__ float hacc[2][HEADS][HID];

    if (node < NN) {
        int beg = offs[node], end = offs[node + 1];
        const int off = w * HID + lane * 4;
        uint2 xrraw = *(const uint2*)(xlr + (size_t)node * 1024 + HOUT + off);
        const __half2 xr01 = *(const __half2*)&xrraw.x, xr23 = *(const __half2*)&xrraw.y;
        float4 a4 = *(const float4*)(att + w * HID + lane * 4);
        const __half2 a01 = __floats2half2_rn(a4.x, a4.y);
        const __half2 a23 = __floats2half2_rn(a4.z, a4.w);
        const __half2 neg2 = __float2half2_rn(NEG_SLOPE);

        float emax = -1e30f, denom = 0.f;
        float4 acc = make_float4(0.f, 0.f, 0.f, 0.f);
        int i = beg;
        for (; i + 3 < end; i += 4) {
            int s0 = __ldg(csr + i),     s1 = __ldg(csr + i + 1);
            int s2 = __ldg(csr + i + 2), s3 = __ldg(csr + i + 3);
            uint2 r0 = *(const uint2*)(xlr + (size_t)s0 * 1024 + off);
            uint2 r1 = *(const uint2*)(xlr + (size_t)s1 * 1024 + off);
            uint2 r2 = *(const uint2*)(xlr + (size_t)s2 * 1024 + off);
            uint2 r3 = *(const uint2*)(xlr + (size_t)s3 * 1024 + off);
            float2 v0a, v0b, v1a, v1b, v2a, v2b, v3a, v3b;
            float p0 = h2dot(a01, a23, xr01, xr23, neg2, r0, &v0a, &v0b);
            float p1 = h2dot(a01, a23, xr01, xr23, neg2, r1, &v1a, &v1b);
            float p2 = h2dot(a01, a23, xr01, xr23, neg2, r2, &v2a, &v2b);
            float p3 = h2dot(a01, a23, xr01, xr23, neg2, r3, &v3a, &v3b);
            #pragma unroll
            for (int o = 16; o; o >>= 1) {
                p0 += __shfl_xor_sync(0xffffffffu, p0, o);
                p1 += __shfl_xor_sync(0xffffffffu, p1, o);
                p2 += __shfl_xor_sync(0xffffffffu, p2, o);
                p3 += __shfl_xor_sync(0xffffffffu, p3, o);
            }
            float nm = fmaxf(fmaxf(emax, fmaxf(p0, p1)), fmaxf(p2, p3));
            float sc = __expf(emax - nm);
            denom *= sc;
            acc.x *= sc; acc.y *= sc; acc.z *= sc; acc.w *= sc;
            emax = nm;
            float w0 = __expf(p0 - nm), w1 = __expf(p1 - nm);
            float w2 = __expf(p2 - nm), w3 = __expf(p3 - nm);
            denom += (w0 + w1) + (w2 + w3);
            acc.x += w0 * v0a.x + w1 * v1a.x + w2 * v2a.x + w3 * v3a.x;
            acc.y += w0 * v0a.y + w1 * v1a.y + w2 * v2a.y + w3 * v3a.y;
            acc.z += w0 * v0b.x + w1 * v1b.x + w2 * v2b.x + w3 * v3b.x;
            acc.w += w0 * v0b.y + w1 * v1b.y + w2 * v2b.y + w3 * v3b.y;
        }
        for (; i < end; i++) {
            int s0 = __ldg(csr + i);
            uint2 r0 = *(const uint2*)(xlr + (size_t)s0 * 1024 + off);
            float2 v0a, v0b;
            float p0 = h2dot(a01, a23, xr01, xr23, neg2, r0, &v0a, &v0b);
            #pragma unroll
            for (int o = 16; o; o >>= 1) p0 += __shfl_xor_sync(0xffffffffu, p0, o);
            float nm = fmaxf(emax, p0);
            float sc = __expf(emax - nm);
            denom *= sc;
            acc.x *= sc; acc.y *= sc; acc.z *= sc; acc.w *= sc;
            emax = nm;
            float w0 = __expf(p0 - nm);
            denom += w0;
            acc.x += w0 * v0a.x; acc.y += w0 * v0a.y;
            acc.z += w0 * v0b.x; acc.w += w0 * v0b.y;
        }
        float inv = denom > 0.f ? 1.f / denom : 0.f;
        hacc[half_][w][lane * 4 + 0] = acc.x * inv;
        hacc[half_][w][lane * 4 + 1] = acc.y * inv;
        hacc[half_][w][lane * 4 + 2] = acc.z * inv;
        hacc[half_][w][lane * 4 + 3] = acc.w * inv;
    }
    __syncthreads();
    if (node < NN) {
        float sv = (hacc[half_][0][t128] + hacc[half_][1][t128] +
                    hacc[half_][2][t128] + hacc[half_][3][t128]) * 0.25f
                 + cbias[t128] + hin[(size_t)node * HID + t128];
        sv = fmaxf(sv, 0.f);
        hout[(size_t)node * HID + t128] = sv;
        houth[(size_t)node * HID + t128] = __float2half(sv);
    }
}

// ---------------- final predictor head (z2 fp32, row stride 128) ----------------
__global__ void k_pred3(const float* __restrict__ z2, const float* __restrict__ W,
                        const float* __restrict__ b, float* __restrict__ out, int n) {
    int warp = (blockIdx.x * blockDim.x + threadIdx.x) >> 5;
    int lane = threadIdx.x & 31;
    if (warp >= n) return;
    const float* zr = z2 + (size_t)warp * 128;
    float p = zr[lane] * W[lane] + zr[lane + 32] * W[lane + 32];
    #pragma unroll
    for (int o = 16; o; o >>= 1) p += __shfl_xor_sync(0xffffffffu, p, o);
    if (lane == 0) {
        float s = p + b[0];
        s = fminf(fmaxf(s, -15.f), 15.f);
        out[warp] = s;
    }
}

// ---------------- launch ----------------
extern "C" void kernel_launch(void* const* d_in, const int* in_sizes, int n_in,
                              void* d_out, int out_size) {
    const float* x      = (const float*)d_in[0];
    const int*   eidx   = (const int*)d_in[1];
    const float* emb_W  = (const float*)d_in[3];
    const float* emb_b  = (const float*)d_in[4];
    const float* Wl     = (const float*)d_in[5];
    const float* bl     = (const float*)d_in[6];
    const float* Wr     = (const float*)d_in[7];
    const float* br     = (const float*)d_in[8];
    const float* att    = (const float*)d_in[9];
    const float* cbias  = (const float*)d_in[10];
    const float* p1_W   = (const float*)d_in[11];
    const float* p1_b   = (const float*)d_in[12];
    const float* p2_W   = (const float*)d_in[13];
    const float* p2_b   = (const float*)d_in[14];
    const float* p3_W   = (const float*)d_in[15];
    const float* p3_b   = (const float*)d_in[16];
    float* out = (float*)d_out;

    const int* srcp = eidx;
    const int* dstp = eidx + EE;

    float *hA, *hB, *zf, *bB, *p2b;
    __half *hAh, *hBh, *xh, *xlrh;
    uint32_t* img;
    int *deg, *offs, *cursor, *csr, *blksum, *blkoff;
    cudaGetSymbolAddress((void**)&hA, g_hA);
    cudaGetSymbolAddress((void**)&hB, g_hB);
    cudaGetSymbolAddress((void**)&hAh, g_hAh);
    cudaGetSymbolAddress((void**)&hBh, g_hBh);
    cudaGetSymbolAddress((void**)&xh, g_xh);
    cudaGetSymbolAddress((void**)&xlrh, g_xlrh);
    cudaGetSymbolAddress((void**)&zf, g_zf);
    cudaGetSymbolAddress((void**)&img, g_img);
    cudaGetSymbolAddress((void**)&bB, g_bB);
    cudaGetSymbolAddress((void**)&p2b, g_p2b);
    cudaGetSymbolAddress((void**)&deg, g_deg);
    cudaGetSymbolAddress((void**)&offs, g_offs);
    cudaGetSymbolAddress((void**)&cursor, g_cursor);
    cudaGetSymbolAddress((void**)&csr, g_csr);
    cudaGetSymbolAddress((void**)&blksum, g_blksum);
    cudaGetSymbolAddress((void**)&blkoff, g_blkoff);

    cudaFuncSetAttribute(k_gemm5<64, 0>,  cudaFuncAttributeMaxDynamicSharedMemorySize, G5_SMEM);
    cudaFuncSetAttribute(k_gemm5<128, 0>, cudaFuncAttributeMaxDynamicSharedMemorySize, G5_SMEM);
    cudaFuncSetAttribute(k_gemm5<128, 1>, cudaFuncAttributeMaxDynamicSharedMemorySize, G5_SMEM);

    const int MB = (NN + 127) / 128;  // 391

    // (1) fp16 fragment images + bias packing
    k_img<<<(IMG_TOTAL + 255) / 256, 256>>>(emb_W, Wl, Wr, p1_W, p2_W, bl, br, p2_b,
                                            img, bB, p2b);
    // (2) x -> fp16
    k_h2<<<(NN * FIN + 255) / 256, 256>>>(x, xh, NN * FIN);
    // (3) embedding
    k_gemm5<64, 0><<<dim3(MB, 1), 128, 2 * STAGE_B>>>(xh, img + IMG_EMB, emb_b, hA, hAh, NN, HID, 1);
    // (4) layer-1 split GEMM  <-- profiled slot
    k_gemm5<128, 1><<<dim3(MB, 8), 128, 4 * STAGE_B>>>(hAh, img + IMG_WB, bB, nullptr, xlrh, NN, 1024, 0);
    // CSR build
    k_zero_int<<<(NN + 255) / 256, 256>>>(deg, NN);
    k_count_deg<<<(EE + 255) / 256, 256>>>(dstp, deg, EE);
    k_scan_part<<<NBLK, SCAN_B>>>(deg, offs, blksum, NN);
    k_scan_blk<<<1, 64>>>(blksum, blkoff, offs, NBLK, NN);
    k_scan_add<<<NBLK, SCAN_B>>>(offs, blkoff, cursor, NN);
    k_fill_csr<<<(EE + 255) / 256, 256>>>(srcp, dstp, cursor, csr, EE);

    // layer 1 edge
    float* hc = hA;   __half* hch = hAh;
    float* hn = hB;   __half* hnh = hBh;
    k_gat_edge<<<(NN + 1) / 2, 256>>>(xlrh, att, cbias, hc, hn, hnh, offs, csr);
    { float* t = hc; hc = hn; hn = t; __half* th = hch; hch = hnh; hnh = th; }

    // layers 2..3
    for (int l = 1; l < LAYERS; l++) {
        k_gemm5<128, 1><<<dim3(MB, 8), 128, 4 * STAGE_B>>>(
            hch, img + IMG_WB + (size_t)l * 65536, bB + (size_t)l * 1024, nullptr, xlrh, NN, 1024, 0);
        k_gat_edge<<<(NN + 1) / 2, 256>>>(xlrh, att + (size_t)l * HEADS * HID,
                                          cbias + l * HID, hc, hn, hnh, offs, csr);
        float* t = hc; hc = hn; hn = t; __half* th = hch; hch = hnh; hnh = th;
    }

    // predictor MLP: z1 fp32+fp16 (z1h reuses xlrh), z2 fp32
    float* z1f = zf;
    __half* z1h = xlrh;
    float* z2 = zf + (size_t)NN * HID;
    k_gemm5<128, 0><<<dim3(MB, 1), 128, 4 * STAGE_B>>>(hch, img + IMG_P1, p1_b, z1f, z1h, NN, HID, 1);
    k_gemm5<128, 0><<<dim3(MB, 1), 128, 4 * STAGE_B>>>(z1h, img + IMG_P2, p2b, z2, nullptr, NN, HID, 1);
    k_pred3<<<(NN * 32 + 255) / 256, 256>>>(z2, p3_W, p3_b, out, NN);
}